// round 7
// baseline (speedup 1.0000x reference)
#include <cuda_runtime.h>
#include <cuda_fp16.h>
#include <math.h>

#define Bc   8
#define Nc   325
#define Tc   24
#define Dc   64
#define Hc   8
#define Mc   16
#define E2c  128
#define BNc  2600   // Bc*Nc
#define PAD  132    // padded row stride for T x E2 fp32 smem tiles

// ---------------- device scratch ----------------
__device__ float g_tfeat[Bc * Mc];                            // (B,16)
__device__ float g_gcn[(size_t)Bc * Nc * Tc * Dc];            // (B,N,T,D) ~16MB
__device__ __align__(16) __half g_weff[(size_t)3 * BNc * E2c * E2c]; // fp16 ~256MB

__device__ __forceinline__ float lrelu(float x) { return x > 0.f ? x : 0.1f * x; }

#define CP_ASYNC16(sdst, gsrc) \
    asm volatile("cp.async.cg.shared.global [%0], [%1], 16;" :: "r"(sdst), "l"(gsrc) : "memory")
#define CP_COMMIT() asm volatile("cp.async.commit_group;" ::: "memory")
#define CP_WAIT0()  asm volatile("cp.async.wait_group 0;" ::: "memory")

__device__ __forceinline__ void ldsm_x4(unsigned* r, unsigned addr) {
    asm volatile("ldmatrix.sync.aligned.m8n8.x4.shared.b16 {%0,%1,%2,%3}, [%4];"
                 : "=r"(r[0]), "=r"(r[1]), "=r"(r[2]), "=r"(r[3]) : "r"(addr));
}
__device__ __forceinline__ void ldsm_x4_t(unsigned* r, unsigned addr) {
    asm volatile("ldmatrix.sync.aligned.m8n8.x4.trans.shared.b16 {%0,%1,%2,%3}, [%4];"
                 : "=r"(r[0]), "=r"(r[1]), "=r"(r[2]), "=r"(r[3]) : "r"(addr));
}
__device__ __forceinline__ void mma16816(float* c, const unsigned* a, unsigned b0, unsigned b1) {
    asm volatile("mma.sync.aligned.m16n8k16.row.col.f32.f16.f16.f32 "
                 "{%0,%1,%2,%3}, {%4,%5,%6,%7}, {%8,%9}, {%0,%1,%2,%3};"
                 : "+f"(c[0]), "+f"(c[1]), "+f"(c[2]), "+f"(c[3])
                 : "r"(a[0]), "r"(a[1]), "r"(a[2]), "r"(a[3]), "r"(b0), "r"(b1));
}

// ---------------- Kernel 1: tfeat ----------------
__global__ void k_tfeat(const float* __restrict__ tXin,
                        const float* __restrict__ tpw,
                        const float* __restrict__ tpb) {
    __shared__ float s_mean[Dc];
    int b = blockIdx.x;
    int d = threadIdx.x;  // 64 threads
    const float* p = tXin + (size_t)b * Nc * Tc * Dc;  // n = 0 slice
    float s = 0.f;
    #pragma unroll
    for (int t = 0; t < Tc; t++) s += p[t * Dc + d];
    s_mean[d] = s * (1.0f / Tc);
    __syncthreads();
    if (d < Mc) {
        float acc = tpb[d];
        #pragma unroll
        for (int i = 0; i < Dc; i++) acc += s_mean[i] * tpw[i * Mc + d];
        g_tfeat[b * Mc + d] = tanhf(acc);
    }
}

// ---------------- Kernel 2: support GEMM + GCN (fused) --------------------------
__global__ __launch_bounds__(256) void k_gcn(const float* __restrict__ matrix,
                                             const float* __restrict__ hidden,
                                             const float* __restrict__ gcn_w,
                                             const float* __restrict__ gcn_b) {
    __shared__ float sA[64][17];
    __shared__ float sB[16][68];
    __shared__ float sS[64][68];
    __shared__ float sW[64][68];
    int tid = threadIdx.x;
    int nt = blockIdx.x, t = blockIdx.y, b = blockIdx.z;
    int n0 = nt * 64;

    for (int idx = tid; idx < 4096; idx += 256) sW[idx >> 6][idx & 63] = gcn_w[idx];

    int ty = tid >> 4, tx = tid & 15;
    int r0 = ty * 4, c0 = tx * 4;
    float acc[4][4] = {};
    const float* Mrow = matrix + ((size_t)(b * Tc + t) * Nc) * Nc;

    for (int kb = 0; kb < 21; kb++) {
        int m0 = kb * 16;
        for (int idx = tid; idx < 1024; idx += 256) {
            int i = idx >> 4, j = idx & 15;
            int n = n0 + i, m = m0 + j;
            sA[i][j] = (n < Nc && m < Nc) ? Mrow[(size_t)n * Nc + m] : 0.f;
        }
        for (int idx = tid; idx < 1024; idx += 256) {
            int j = idx >> 6, d = idx & 63;
            int m = m0 + j;
            sB[j][d] = (m < Nc) ? hidden[((size_t)(b * Nc + m) * Tc + t) * Dc + d] : 0.f;
        }
        __syncthreads();
        #pragma unroll
        for (int j = 0; j < 16; j++) {
            float a0 = sA[r0][j], a1 = sA[r0 + 1][j], a2 = sA[r0 + 2][j], a3 = sA[r0 + 3][j];
            float4 bb = *(const float4*)&sB[j][c0];
            acc[0][0] += a0 * bb.x; acc[0][1] += a0 * bb.y; acc[0][2] += a0 * bb.z; acc[0][3] += a0 * bb.w;
            acc[1][0] += a1 * bb.x; acc[1][1] += a1 * bb.y; acc[1][2] += a1 * bb.z; acc[1][3] += a1 * bb.w;
            acc[2][0] += a2 * bb.x; acc[2][1] += a2 * bb.y; acc[2][2] += a2 * bb.z; acc[2][3] += a2 * bb.w;
            acc[3][0] += a3 * bb.x; acc[3][1] += a3 * bb.y; acc[3][2] += a3 * bb.z; acc[3][3] += a3 * bb.w;
        }
        __syncthreads();
    }
    #pragma unroll
    for (int rr = 0; rr < 4; rr++)
        *(float4*)&sS[r0 + rr][c0] = make_float4(acc[rr][0], acc[rr][1], acc[rr][2], acc[rr][3]);
    __syncthreads();

    float acc2[4][4] = {};
    #pragma unroll
    for (int d = 0; d < 64; d++) {
        float a0 = sS[r0][d], a1 = sS[r0 + 1][d], a2 = sS[r0 + 2][d], a3 = sS[r0 + 3][d];
        float4 w = *(const float4*)&sW[d][c0];
        acc2[0][0] += a0 * w.x; acc2[0][1] += a0 * w.y; acc2[0][2] += a0 * w.z; acc2[0][3] += a0 * w.w;
        acc2[1][0] += a1 * w.x; acc2[1][1] += a1 * w.y; acc2[1][2] += a1 * w.z; acc2[1][3] += a1 * w.w;
        acc2[2][0] += a2 * w.x; acc2[2][1] += a2 * w.y; acc2[2][2] += a2 * w.z; acc2[2][3] += a2 * w.w;
        acc2[3][0] += a3 * w.x; acc2[3][1] += a3 * w.y; acc2[3][2] += a3 * w.z; acc2[3][3] += a3 * w.w;
    }
    float4 gb = *(const float4*)&gcn_b[c0];
    #pragma unroll
    for (int rr = 0; rr < 4; rr++) {
        int n = n0 + r0 + rr;
        if (n < Nc) {
            float4 o;
            o.x = fmaxf(acc2[rr][0] + gb.x, 0.f);
            o.y = fmaxf(acc2[rr][1] + gb.y, 0.f);
            o.z = fmaxf(acc2[rr][2] + gb.z, 0.f);
            o.w = fmaxf(acc2[rr][3] + gb.w, 0.f);
            *(float4*)&g_gcn[((size_t)(b * Nc + n) * Tc + t) * Dc + c0] = o;
        }
    }
}

// ---------------- Kernel 3: Weff build (fp16 out), W in regs, 32 rows/block -----
__global__ __launch_bounds__(256) void k_weff(const float* __restrict__ WQ,
                                              const float* __restrict__ WK,
                                              const float* __restrict__ WV,
                                              const float* __restrict__ node_emb) {
    __shared__ float s_emb[32][16];
    int tid = threadIdx.x;
    int cx = blockIdx.x;   // 16 chunks of 1024 cols
    int by = blockIdx.y;   // 82 groups of 32 bn rows
    int X  = blockIdx.z;   // 0=Q,1=K,2=V
    const float* W = (X == 0) ? WQ : (X == 1) ? WK : WV;
    int c0 = cx * 1024 + tid * 4;

    float4 w[16];
    #pragma unroll
    for (int m = 0; m < 16; m++) w[m] = *(const float4*)&W[(size_t)m * 16384 + c0];

    for (int idx = tid; idx < 512; idx += 256) {
        int row = idx >> 4, m = idx & 15;
        int bn = by * 32 + row;
        if (bn < BNc) {
            int b = bn / Nc, n = bn - b * Nc;
            s_emb[row][m] = node_emb[n * Mc + m] * g_tfeat[b * Mc + m];
        }
    }
    __syncthreads();

    #pragma unroll 4
    for (int row = 0; row < 32; row++) {
        int bn = by * 32 + row;
        if (bn >= BNc) break;
        float4 acc = make_float4(0.f, 0.f, 0.f, 0.f);
        #pragma unroll
        for (int m = 0; m < 16; m++) {
            float e = s_emb[row][m];
            acc.x += e * w[m].x; acc.y += e * w[m].y;
            acc.z += e * w[m].z; acc.w += e * w[m].w;
        }
        __half2 h0 = __floats2half2_rn(acc.x, acc.y);
        __half2 h1 = __floats2half2_rn(acc.z, acc.w);
        __half2* dst = (__half2*)&g_weff[((size_t)X * BNc + bn) * 16384 + c0];
        dst[0] = h0; dst[1] = h1;
    }
}

// ---------------- Kernel 4: fused per-(b,n) attention path ----------------------
// smem (float units), total 14120 floats = 56480B (4 CTAs/SM):
//   phase1: s_act fp16 32x136  [0,2176) | s_w fp16 2buf x 16x136 rows [2176,4352)
//   phase2: s_sc overlay [0,4616)
//   s_q [4616,7784) | s_val overlay
//   s_k [7784,10952)
//   s_v [10952,14120) | s_value [10952,12488) + s_gcn [12488,14024) overlay
#define ATTN_SMEM_FLOATS 14120
#define ATTN_SMEM_BYTES  (ATTN_SMEM_FLOATS * 4)

__global__ __launch_bounds__(256, 4) void k_attn(const float* __restrict__ hidden,
                                                 const float* __restrict__ tXin,
                                                 const float* __restrict__ out_w,
                                                 const float* __restrict__ out_b,
                                                 const float* __restrict__ gate_w,
                                                 const float* __restrict__ gate_b,
                                                 float* __restrict__ out) {
    extern __shared__ float sm[];
    __half* s_act  = (__half*)sm;      // 32x136 halfs
    float* s_sc    = sm;               // overlay 8*577
    float* s_q     = sm + 4616;
    float* s_k     = sm + 7784;
    float* s_v     = sm + 10952;
    float* s_val   = s_q;              // overlay after scores
    float* s_value = sm + 10952;       // overlay after AV
    float* s_gcn   = sm + 12488;       // overlay after AV

    int tid  = threadIdx.x;
    int lane = tid & 31;
    int warp = tid >> 5;
    int bn   = blockIdx.x;
    size_t base = (size_t)bn * (Tc * Dc);

    // ---- stage activations as fp16 (rows 24-31 zero) ----
    for (int idx = tid; idx < 4096; idx += 256) {
        int t = idx >> 7, i = idx & 127;
        float vv = 0.f;
        if (t < Tc) vv = (i < 64) ? hidden[base + t * 64 + i] : tXin[base + t * 64 + (i - 64)];
        s_act[t * 136 + i] = __float2half(vv);
    }

    const __half* wq = g_weff + (size_t)bn * 16384;
    const __half* wk = g_weff + ((size_t)BNc + bn) * 16384;
    const __half* wv = g_weff + ((size_t)2 * BNc + bn) * 16384;

    unsigned act_base = (unsigned)__cvta_generic_to_shared(s_act);
    unsigned w_base   = act_base + 8704;   // s_w starts at float 2176

    // weight stage: 16 i-rows x 128 halfs, padded rows 272B; 256 transfers = 1/thread
    int srow = tid >> 4, sseg = tid & 15;
    unsigned sdst_off = srow * 272 + sseg * 16;
    int ssrc_off = srow * 128 + sseg * 8;

    // prefetch stage 0 (X=0, i0=0) into buf 0
    CP_ASYNC16(w_base + sdst_off, wq + ssrc_off);
    CP_COMMIT();

    // ldmatrix per-lane offsets
    int arow = (lane & 7) + (lane & 8);          // 0..15
    int acol = (lane & 16) ? 8 : 0;
    unsigned a_off0 = (arow * 136 + acol) * 2;               // mt=0
    unsigned a_off1 = ((16 + arow) * 136 + acol) * 2;        // mt=1
    int wn = warp * 16;
    unsigned b_off = (arow * 136 + wn + acol) * 2;           // within stage buf

    int trow = lane >> 2, tcol = (lane & 3) * 2;

    // ---- QKV projection: single-sync double-buffered pipeline, 24 stages ----
    for (int X = 0; X < 3; X++) {
        float acc[2][2][4] = {};   // [nt][mt][4]
        for (int kk = 0; kk < 8; kk++) {
            int s = X * 8 + kk;
            int buf = s & 1;
            CP_WAIT0();            // stage s landed (only pending group)
            __syncthreads();       // all threads done with slot buf^1 (stage s-1)
            if (s < 23) {          // prefetch stage s+1 into slot buf^1 (safe post-sync)
                int s1 = s + 1;
                int X1 = s1 >> 3, i0 = (s1 & 7) * 16;
                const __half* w = (X1 == 0) ? wq : (X1 == 1) ? wk : wv;
                CP_ASYNC16(w_base + (buf ^ 1) * 4352 + sdst_off, w + i0 * 128 + ssrc_off);
                CP_COMMIT();
            }
            unsigned a0f[4], a1f[4], bf[4];
            ldsm_x4(a0f, act_base + a_off0 + kk * 32);
            ldsm_x4(a1f, act_base + a_off1 + kk * 32);
            ldsm_x4_t(bf, w_base + buf * 4352 + b_off);
            mma16816(acc[0][0], a0f, bf[0], bf[1]);
            mma16816(acc[0][1], a1f, bf[0], bf[1]);
            mma16816(acc[1][0], a0f, bf[2], bf[3]);
            mma16816(acc[1][1], a1f, bf[2], bf[3]);
        }
        // store lrelu(result) to s_q/k/v
        float* dst = (X == 0) ? s_q : (X == 1) ? s_k : s_v;
        #pragma unroll
        for (int nt = 0; nt < 2; nt++) {
            int colb = wn + nt * 8 + tcol;
            {   // mt = 0: rows trow, trow+8
                float* c = acc[nt][0];
                *(float2*)&dst[trow * PAD + colb] = make_float2(lrelu(c[0]), lrelu(c[1]));
                *(float2*)&dst[(trow + 8) * PAD + colb] = make_float2(lrelu(c[2]), lrelu(c[3]));
            }
            {   // mt = 1: rows 16+trow only (24+trow is padding)
                float* c = acc[nt][1];
                *(float2*)&dst[(16 + trow) * PAD + colb] = make_float2(lrelu(c[0]), lrelu(c[1]));
            }
        }
    }
    __syncthreads();

    // ---- scores (causal), float4 dot products: overlay region [0,4616) ----
    for (int idx = tid; idx < 4608; idx += 256) {
        int h = idx / 576; int r = idx - h * 576; int t = r / 24; int s = r - t * 24;
        if (s <= t) {
            const float4* qp = (const float4*)&s_q[t * PAD + h * 16];
            const float4* kp = (const float4*)&s_k[s * PAD + h * 16];
            float d = 0.f;
            #pragma unroll
            for (int e = 0; e < 4; e++) {
                float4 q4 = qp[e], k4 = kp[e];
                d += q4.x * k4.x + q4.y * k4.y + q4.z * k4.z + q4.w * k4.w;
            }
            s_sc[h * 577 + t * 24 + s] = 0.25f * d;  // 1/sqrt(16)
        }
    }
    __syncthreads();

    // ---- softmax per (h,t) row ----
    if (tid < 192) {
        int h = tid / 24, t = tid % 24;
        float* row = &s_sc[h * 577 + t * 24];
        float mx = -1e30f;
        for (int s = 0; s <= t; s++) mx = fmaxf(mx, row[s]);
        float sum = 0.f;
        for (int s = 0; s <= t; s++) { float e = expf(row[s] - mx); row[s] = e; sum += e; }
        float inv = 1.f / sum;
        for (int s = 0; s < Tc; s++) row[s] = (s <= t) ? row[s] * inv : 0.f;
    }
    __syncthreads();

    // ---- val = attn @ v, float4 (writes overlay over s_q) ----
    {
        int kg = tid & 31, tg = tid >> 5;   // 32 col-groups(4) x 8 t-groups(3)
        int c0 = kg * 4;
        int h = kg >> 2;
        int tg3 = tg * 3;
        float4 a2[3] = {};
        #pragma unroll
        for (int s = 0; s < Tc; s++) {
            float4 v4 = *(const float4*)&s_v[s * PAD + c0];
            #pragma unroll
            for (int r = 0; r < 3; r++) {
                float a = s_sc[h * 577 + (tg3 + r) * 24 + s];
                a2[r].x += a * v4.x; a2[r].y += a * v4.y;
                a2[r].z += a * v4.z; a2[r].w += a * v4.w;
            }
        }
        __syncthreads();
        #pragma unroll
        for (int r = 0; r < 3; r++)
            *(float4*)&s_val[(tg3 + r) * PAD + c0] = a2[r];
    }
    __syncthreads();

    // ---- load gcn under out-proj compute (s_v region now dead) ----
    for (int idx = tid; idx < 1536; idx += 256) s_gcn[idx] = g_gcn[base + idx];

    // ---- value = lrelu(val @ out_w + out_b) ----
    int e0 = (tid & 15) * 4;
    int tg2 = tid >> 4;               // 0..15
    int t0 = tg2, t1 = tg2 + 16;
    int t1c = (t1 < Tc) ? t1 : 0;
    {
        float a0[4] = {}, a1[4] = {};
        #pragma unroll 2
        for (int i = 0; i < 128; i += 4) {
            float4 x0 = *(const float4*)&s_val[t0 * PAD + i];
            float4 x1 = *(const float4*)&s_val[t1c * PAD + i];
            #pragma unroll
            for (int u = 0; u < 4; u++) {
                float4 w4 = *(const float4*)&out_w[(i + u) * 64 + e0];
                float xu0 = (&x0.x)[u], xu1 = (&x1.x)[u];
                a0[0] += xu0 * w4.x; a0[1] += xu0 * w4.y; a0[2] += xu0 * w4.z; a0[3] += xu0 * w4.w;
                a1[0] += xu1 * w4.x; a1[1] += xu1 * w4.y; a1[2] += xu1 * w4.z; a1[3] += xu1 * w4.w;
            }
        }
        float4 ob = *(const float4*)&out_b[e0];
        float4 v0;
        v0.x = lrelu(a0[0] + ob.x); v0.y = lrelu(a0[1] + ob.y);
        v0.z = lrelu(a0[2] + ob.z); v0.w = lrelu(a0[3] + ob.w);
        *(float4*)&s_value[t0 * 64 + e0] = v0;
        if (t1 < Tc) {
            float4 v1;
            v1.x = lrelu(a1[0] + ob.x); v1.y = lrelu(a1[1] + ob.y);
            v1.z = lrelu(a1[2] + ob.z); v1.w = lrelu(a1[3] + ob.w);
            *(float4*)&s_value[t1 * 64 + e0] = v1;
        }
    }
    __syncthreads();

    // ---- gate + blend + residual ----
    {
        float g0[4] = {}, g1[4] = {};
        #pragma unroll 2
        for (int i = 0; i < 64; i += 4) {
            float4 x0 = *(const float4*)&s_gcn[t0 * 64 + i];
            float4 x1 = *(const float4*)&s_gcn[t1c * 64 + i];
            #pragma unroll
            for (int u = 0; u < 4; u++) {
                float4 w4 = *(const float4*)&gate_w[(i + u) * 64 + e0];
                float xu0 = (&x0.x)[u], xu1 = (&x1.x)[u];
                g0[0] += xu0 * w4.x; g0[1] += xu0 * w4.y; g0[2] += xu0 * w4.z; g0[3] += xu0 * w4.w;
                g1[0] += xu1 * w4.x; g1[1] += xu1 * w4.y; g1[2] += xu1 * w4.z; g1[3] += xu1 * w4.w;
            }
        }
        #pragma unroll 2
        for (int i = 0; i < 64; i += 4) {
            float4 x0 = *(const float4*)&s_value[t0 * 64 + i];
            float4 x1 = *(const float4*)&s_value[t1c * 64 + i];
            #pragma unroll
            for (int u = 0; u < 4; u++) {
                float4 w4 = *(const float4*)&gate_w[(64 + i + u) * 64 + e0];
                float xu0 = (&x0.x)[u], xu1 = (&x1.x)[u];
                g0[0] += xu0 * w4.x; g0[1] += xu0 * w4.y; g0[2] += xu0 * w4.z; g0[3] += xu0 * w4.w;
                g1[0] += xu1 * w4.x; g1[1] += xu1 * w4.y; g1[2] += xu1 * w4.z; g1[3] += xu1 * w4.w;
            }
        }
        float4 gb = *(const float4*)&gate_b[e0];
        {
            float4 hd = *(const float4*)&hidden[base + t0 * 64 + e0];
            float zx = 1.f / (1.f + expf(-(g0[0] + gb.x)));
            float zy = 1.f / (1.f + expf(-(g0[1] + gb.y)));
            float zz = 1.f / (1.f + expf(-(g0[2] + gb.z)));
            float zw = 1.f / (1.f + expf(-(g0[3] + gb.w)));
            const float* gc = &s_gcn[t0 * 64 + e0];
            const float* vv = &s_value[t0 * 64 + e0];
            float4 o;
            o.x = zx * gc[0] + (1.f - zx) * vv[0] + hd.x;
            o.y = zy * gc[1] + (1.f - zy) * vv[1] + hd.y;
            o.z = zz * gc[2] + (1.f - zz) * vv[2] + hd.z;
            o.w = zw * gc[3] + (1.f - zw) * vv[3] + hd.w;
            *(float4*)&out[base + t0 * 64 + e0] = o;
        }
        if (t1 < Tc) {
            float4 hd = *(const float4*)&hidden[base + t1 * 64 + e0];
            float zx = 1.f / (1.f + expf(-(g1[0] + gb.x)));
            float zy = 1.f / (1.f + expf(-(g1[1] + gb.y)));
            float zz = 1.f / (1.f + expf(-(g1[2] + gb.z)));
            float zw = 1.f / (1.f + expf(-(g1[3] + gb.w)));
            const float* gc = &s_gcn[t1 * 64 + e0];
            const float* vv = &s_value[t1 * 64 + e0];
            float4 o;
            o.x = zx * gc[0] + (1.f - zx) * vv[0] + hd.x;
            o.y = zy * gc[1] + (1.f - zy) * vv[1] + hd.y;
            o.z = zz * gc[2] + (1.f - zz) * vv[2] + hd.z;
            o.w = zw * gc[3] + (1.f - zw) * vv[3] + hd.w;
            *(float4*)&out[base + t1 * 64 + e0] = o;
        }
    }
}

// ---------------- launch ----------------
extern "C" void kernel_launch(void* const* d_in, const int* in_sizes, int n_in,
                              void* d_out, int out_size) {
    const float* hidden   = (const float*)d_in[0];
    const float* tXin     = (const float*)d_in[1];
    const float* matrix   = (const float*)d_in[2];
    const float* gcn_w    = (const float*)d_in[3];
    const float* gcn_b    = (const float*)d_in[4];
    const float* node_emb = (const float*)d_in[5];
    const float* tproj_w  = (const float*)d_in[6];
    const float* tproj_b  = (const float*)d_in[7];
    const float* WK       = (const float*)d_in[8];
    const float* WQ       = (const float*)d_in[9];
    const float* WV       = (const float*)d_in[10];
    const float* out_w    = (const float*)d_in[11];
    const float* out_b    = (const float*)d_in[12];
    const float* gate_w   = (const float*)d_in[13];
    const float* gate_b   = (const float*)d_in[14];
    float* out = (float*)d_out;

    cudaFuncSetAttribute(k_attn, cudaFuncAttributeMaxDynamicSharedMemorySize, ATTN_SMEM_BYTES);

    k_tfeat<<<Bc, 64>>>(tXin, tproj_w, tproj_b);
    k_gcn<<<dim3(6, Tc, Bc), 256>>>(matrix, hidden, gcn_w, gcn_b);
    k_weff<<<dim3(16, 82, 3), 256>>>(WQ, WK, WV, node_emb);
    k_attn<<<BNc, 256, ATTN_SMEM_BYTES>>>(hidden, tXin, out_w, out_b, gate_w, gate_b, out);
}

// round 8
// speedup vs baseline: 1.1398x; 1.1398x over previous
#include <cuda_runtime.h>
#include <cuda_fp16.h>
#include <math.h>

#define Bc   8
#define Nc   325
#define Tc   24
#define Dc   64
#define Hc   8
#define Mc   16
#define E2c  128
#define BNc  2600   // Bc*Nc
#define PAD  132    // padded row stride for T x E2 fp32 smem tiles

// ---------------- device scratch ----------------
__device__ float g_tfeat[Bc * Mc];                            // (B,16)
__device__ float g_gcn[(size_t)Bc * Nc * Tc * Dc];            // (B,N,T,D) ~16MB
__device__ __align__(16) __half g_weff[(size_t)3 * BNc * E2c * E2c]; // fp16 ~256MB

__device__ __forceinline__ float lrelu(float x) { return x > 0.f ? x : 0.1f * x; }

#define CP_ASYNC16(sdst, gsrc) \
    asm volatile("cp.async.cg.shared.global [%0], [%1], 16;" :: "r"(sdst), "l"(gsrc) : "memory")
#define CP_COMMIT() asm volatile("cp.async.commit_group;" ::: "memory")
#define CP_WAIT1()  asm volatile("cp.async.wait_group 1;" ::: "memory")
#define CP_WAIT0()  asm volatile("cp.async.wait_group 0;" ::: "memory")

__device__ __forceinline__ void ldsm_x4(unsigned* r, unsigned addr) {
    asm volatile("ldmatrix.sync.aligned.m8n8.x4.shared.b16 {%0,%1,%2,%3}, [%4];"
                 : "=r"(r[0]), "=r"(r[1]), "=r"(r[2]), "=r"(r[3]) : "r"(addr));
}
__device__ __forceinline__ void ldsm_x4_t(unsigned* r, unsigned addr) {
    asm volatile("ldmatrix.sync.aligned.m8n8.x4.trans.shared.b16 {%0,%1,%2,%3}, [%4];"
                 : "=r"(r[0]), "=r"(r[1]), "=r"(r[2]), "=r"(r[3]) : "r"(addr));
}
__device__ __forceinline__ void mma16816(float* c, const unsigned* a, unsigned b0, unsigned b1) {
    asm volatile("mma.sync.aligned.m16n8k16.row.col.f32.f16.f16.f32 "
                 "{%0,%1,%2,%3}, {%4,%5,%6,%7}, {%8,%9}, {%0,%1,%2,%3};"
                 : "+f"(c[0]), "+f"(c[1]), "+f"(c[2]), "+f"(c[3])
                 : "r"(a[0]), "r"(a[1]), "r"(a[2]), "r"(a[3]), "r"(b0), "r"(b1));
}
__device__ __forceinline__ unsigned packh2(float a, float b) {
    __half2 h = __floats2half2_rn(a, b);
    return *reinterpret_cast<unsigned*>(&h);
}

// ---------------- Kernel 1: tfeat ----------------
__global__ void k_tfeat(const float* __restrict__ tXin,
                        const float* __restrict__ tpw,
                        const float* __restrict__ tpb) {
    __shared__ float s_mean[Dc];
    int b = blockIdx.x;
    int d = threadIdx.x;  // 64 threads
    const float* p = tXin + (size_t)b * Nc * Tc * Dc;  // n = 0 slice
    float s = 0.f;
    #pragma unroll
    for (int t = 0; t < Tc; t++) s += p[t * Dc + d];
    s_mean[d] = s * (1.0f / Tc);
    __syncthreads();
    if (d < Mc) {
        float acc = tpb[d];
        #pragma unroll
        for (int i = 0; i < Dc; i++) acc += s_mean[i] * tpw[i * Mc + d];
        g_tfeat[b * Mc + d] = tanhf(acc);
    }
}

// ---------------- Kernel 2: support GEMM + GCN (fused) --------------------------
__global__ __launch_bounds__(256) void k_gcn(const float* __restrict__ matrix,
                                             const float* __restrict__ hidden,
                                             const float* __restrict__ gcn_w,
                                             const float* __restrict__ gcn_b) {
    __shared__ float sA[64][17];
    __shared__ float sB[16][68];
    __shared__ float sS[64][68];
    __shared__ float sW[64][68];
    int tid = threadIdx.x;
    int nt = blockIdx.x, t = blockIdx.y, b = blockIdx.z;
    int n0 = nt * 64;

    for (int idx = tid; idx < 4096; idx += 256) sW[idx >> 6][idx & 63] = gcn_w[idx];

    int ty = tid >> 4, tx = tid & 15;
    int r0 = ty * 4, c0 = tx * 4;
    float acc[4][4] = {};
    const float* Mrow = matrix + ((size_t)(b * Tc + t) * Nc) * Nc;

    for (int kb = 0; kb < 21; kb++) {
        int m0 = kb * 16;
        for (int idx = tid; idx < 1024; idx += 256) {
            int i = idx >> 4, j = idx & 15;
            int n = n0 + i, m = m0 + j;
            sA[i][j] = (n < Nc && m < Nc) ? Mrow[(size_t)n * Nc + m] : 0.f;
        }
        for (int idx = tid; idx < 1024; idx += 256) {
            int j = idx >> 6, d = idx & 63;
            int m = m0 + j;
            sB[j][d] = (m < Nc) ? hidden[((size_t)(b * Nc + m) * Tc + t) * Dc + d] : 0.f;
        }
        __syncthreads();
        #pragma unroll
        for (int j = 0; j < 16; j++) {
            float a0 = sA[r0][j], a1 = sA[r0 + 1][j], a2 = sA[r0 + 2][j], a3 = sA[r0 + 3][j];
            float4 bb = *(const float4*)&sB[j][c0];
            acc[0][0] += a0 * bb.x; acc[0][1] += a0 * bb.y; acc[0][2] += a0 * bb.z; acc[0][3] += a0 * bb.w;
            acc[1][0] += a1 * bb.x; acc[1][1] += a1 * bb.y; acc[1][2] += a1 * bb.z; acc[1][3] += a1 * bb.w;
            acc[2][0] += a2 * bb.x; acc[2][1] += a2 * bb.y; acc[2][2] += a2 * bb.z; acc[2][3] += a2 * bb.w;
            acc[3][0] += a3 * bb.x; acc[3][1] += a3 * bb.y; acc[3][2] += a3 * bb.z; acc[3][3] += a3 * bb.w;
        }
        __syncthreads();
    }
    #pragma unroll
    for (int rr = 0; rr < 4; rr++)
        *(float4*)&sS[r0 + rr][c0] = make_float4(acc[rr][0], acc[rr][1], acc[rr][2], acc[rr][3]);
    __syncthreads();

    float acc2[4][4] = {};
    #pragma unroll
    for (int d = 0; d < 64; d++) {
        float a0 = sS[r0][d], a1 = sS[r0 + 1][d], a2 = sS[r0 + 2][d], a3 = sS[r0 + 3][d];
        float4 w = *(const float4*)&sW[d][c0];
        acc2[0][0] += a0 * w.x; acc2[0][1] += a0 * w.y; acc2[0][2] += a0 * w.z; acc2[0][3] += a0 * w.w;
        acc2[1][0] += a1 * w.x; acc2[1][1] += a1 * w.y; acc2[1][2] += a1 * w.z; acc2[1][3] += a1 * w.w;
        acc2[2][0] += a2 * w.x; acc2[2][1] += a2 * w.y; acc2[2][2] += a2 * w.z; acc2[2][3] += a2 * w.w;
        acc2[3][0] += a3 * w.x; acc2[3][1] += a3 * w.y; acc2[3][2] += a3 * w.z; acc2[3][3] += a3 * w.w;
    }
    float4 gb = *(const float4*)&gcn_b[c0];
    #pragma unroll
    for (int rr = 0; rr < 4; rr++) {
        int n = n0 + r0 + rr;
        if (n < Nc) {
            float4 o;
            o.x = fmaxf(acc2[rr][0] + gb.x, 0.f);
            o.y = fmaxf(acc2[rr][1] + gb.y, 0.f);
            o.z = fmaxf(acc2[rr][2] + gb.z, 0.f);
            o.w = fmaxf(acc2[rr][3] + gb.w, 0.f);
            *(float4*)&g_gcn[((size_t)(b * Nc + n) * Tc + t) * Dc + c0] = o;
        }
    }
}

// ---------------- Kernel 3: Weff build (fp16 out), W in regs, 32 rows/block -----
__global__ __launch_bounds__(256) void k_weff(const float* __restrict__ WQ,
                                              const float* __restrict__ WK,
                                              const float* __restrict__ WV,
                                              const float* __restrict__ node_emb) {
    __shared__ float s_emb[32][16];
    int tid = threadIdx.x;
    int cx = blockIdx.x;   // 16 chunks of 1024 cols
    int by = blockIdx.y;   // 82 groups of 32 bn rows
    int X  = blockIdx.z;   // 0=Q,1=K,2=V
    const float* W = (X == 0) ? WQ : (X == 1) ? WK : WV;
    int c0 = cx * 1024 + tid * 4;

    float4 w[16];
    #pragma unroll
    for (int m = 0; m < 16; m++) w[m] = *(const float4*)&W[(size_t)m * 16384 + c0];

    for (int idx = tid; idx < 512; idx += 256) {
        int row = idx >> 4, m = idx & 15;
        int bn = by * 32 + row;
        if (bn < BNc) {
            int b = bn / Nc, n = bn - b * Nc;
            s_emb[row][m] = node_emb[n * Mc + m] * g_tfeat[b * Mc + m];
        }
    }
    __syncthreads();

    #pragma unroll 4
    for (int row = 0; row < 32; row++) {
        int bn = by * 32 + row;
        if (bn >= BNc) break;
        float4 acc = make_float4(0.f, 0.f, 0.f, 0.f);
        #pragma unroll
        for (int m = 0; m < 16; m++) {
            float e = s_emb[row][m];
            acc.x += e * w[m].x; acc.y += e * w[m].y;
            acc.z += e * w[m].z; acc.w += e * w[m].w;
        }
        __half2 h0 = __floats2half2_rn(acc.x, acc.y);
        __half2 h1 = __floats2half2_rn(acc.z, acc.w);
        __half2* dst = (__half2*)&g_weff[((size_t)X * BNc + bn) * 16384 + c0];
        dst[0] = h0; dst[1] = h1;
    }
}

// ---------------- Kernel 4: fused per-(b,n) attention path ----------------------
// smem (float units), total 13952 floats = 55808B (4 CTAs/SM):
//   [0, 2176)      s_act fp16 32x136 (proj phase)  | s_val fp32 overlay [0,3168) after
//   [2176, 4352)   s_w fp16 2buf (proj phase)      |   (overlay continues)
//   [4352, 6528)   s_qh fp16 32x136
//   [6528, 8704)   s_kh fp16 32x136
//   [8704, 10880)  s_vh fp16 32x136
//   [10880, 12416) s_value fp32 24x64
//   [12416, 13952) s_gcn  fp32 24x64
#define ATTN_SMEM_FLOATS 13952
#define ATTN_SMEM_BYTES  (ATTN_SMEM_FLOATS * 4)

__global__ __launch_bounds__(256, 4) void k_attn(const float* __restrict__ hidden,
                                                 const float* __restrict__ tXin,
                                                 const float* __restrict__ out_w,
                                                 const float* __restrict__ out_b,
                                                 const float* __restrict__ gate_w,
                                                 const float* __restrict__ gate_b,
                                                 float* __restrict__ out) {
    extern __shared__ float sm[];
    __half* s_act  = (__half*)sm;              // 32x136 halfs
    __half* s_qh   = (__half*)(sm + 4352);
    __half* s_kh   = (__half*)(sm + 6528);
    __half* s_vh   = (__half*)(sm + 8704);
    float* s_val   = sm;                       // fp32 24xPAD overlay (proj-phase area dead)
    float* s_value = sm + 10880;               // 24x64
    float* s_gcn   = sm + 12416;               // 24x64

    int tid  = threadIdx.x;
    int lane = tid & 31;
    int warp = tid >> 5;
    int bn   = blockIdx.x;
    size_t base = (size_t)bn * (Tc * Dc);

    // ---- stage activations as fp16 (rows 24-31 zero) ----
    for (int idx = tid; idx < 4096; idx += 256) {
        int t = idx >> 7, i = idx & 127;
        float vv = 0.f;
        if (t < Tc) vv = (i < 64) ? hidden[base + t * 64 + i] : tXin[base + t * 64 + (i - 64)];
        s_act[t * 136 + i] = __float2half(vv);
    }

    const __half* wq = g_weff + (size_t)bn * 16384;
    const __half* wk = g_weff + ((size_t)BNc + bn) * 16384;
    const __half* wv = g_weff + ((size_t)2 * BNc + bn) * 16384;

    unsigned act_base = (unsigned)__cvta_generic_to_shared(s_act);
    unsigned w_base   = act_base + 8704;   // s_w at float 2176

    // weight stage: 16 i-rows x 128 halfs, padded rows 272B; 256 transfers = 1/thread
    int srow = tid >> 4, sseg = tid & 15;
    unsigned sdst_off = srow * 272 + sseg * 16;
    int ssrc_off = srow * 128 + sseg * 8;

    // prefetch stage 0 (X=0, i0=0) into buf 0
    CP_ASYNC16(w_base + sdst_off, wq + ssrc_off);
    CP_COMMIT();

    // ldmatrix per-lane offsets
    int arow = (lane & 7) + (lane & 8);          // 0..15
    int acol = (lane & 16) ? 8 : 0;
    unsigned a_off0 = (arow * 136 + acol) * 2;               // act rows 0-15
    unsigned a_off1 = ((16 + arow) * 136 + acol) * 2;        // act rows 16-31
    int wn = warp * 16;
    unsigned b_off = (arow * 136 + wn + acol) * 2;           // within weight stage buf

    int trow = lane >> 2, tcol = (lane & 3) * 2;

    // ---- QKV projection (round-6 pipeline: prefetch -> wait1 -> sync -> mma -> sync) ----
    int buf = 0;
    for (int X = 0; X < 3; X++) {
        float acc[2][2][4] = {};   // [nt][mt][4]
        for (int kk = 0; kk < 8; kk++) {
            int s = X * 8 + kk;
            if (s < 23) {
                int s1 = s + 1;
                int X1 = s1 >> 3, i0 = (s1 & 7) * 16;
                const __half* w = (X1 == 0) ? wq : (X1 == 1) ? wk : wv;
                CP_ASYNC16(w_base + (buf ^ 1) * 4352 + sdst_off, w + i0 * 128 + ssrc_off);
                CP_COMMIT();
                CP_WAIT1();
            } else {
                CP_WAIT0();
            }
            __syncthreads();

            unsigned a0f[4], a1f[4], bf[4];
            ldsm_x4(a0f, act_base + a_off0 + kk * 32);
            ldsm_x4(a1f, act_base + a_off1 + kk * 32);
            ldsm_x4_t(bf, w_base + buf * 4352 + b_off);
            mma16816(acc[0][0], a0f, bf[0], bf[1]);
            mma16816(acc[0][1], a1f, bf[0], bf[1]);
            mma16816(acc[1][0], a0f, bf[2], bf[3]);
            mma16816(acc[1][1], a1f, bf[2], bf[3]);

            __syncthreads();
            buf ^= 1;
        }
        // store lrelu(result) as fp16 to s_qh/s_kh/s_vh (rows 0-23 only)
        __half* dst = (X == 0) ? s_qh : (X == 1) ? s_kh : s_vh;
        #pragma unroll
        for (int nt = 0; nt < 2; nt++) {
            int colb = wn + nt * 8 + tcol;
            float* c0p = acc[nt][0];
            *(__half2*)&dst[trow * 136 + colb] = __floats2half2_rn(lrelu(c0p[0]), lrelu(c0p[1]));
            *(__half2*)&dst[(trow + 8) * 136 + colb] = __floats2half2_rn(lrelu(c0p[2]), lrelu(c0p[3]));
            float* c1p = acc[nt][1];
            *(__half2*)&dst[(16 + trow) * 136 + colb] = __floats2half2_rn(lrelu(c1p[0]), lrelu(c1p[1]));
        }
    }

    // ================= warp-local attention: head h = warp ======================
    {
        int h = warp;
        // zero v rows 24..31 for this head's columns (k-dim contraction safety)
        {
            int r = 24 + (lane >> 2);
            int cu = (lane & 3) * 2;
            unsigned* vz = (unsigned*)s_vh;
            vz[r * 68 + h * 8 + cu]     = 0u;
            vz[r * 68 + h * 8 + cu + 1] = 0u;
        }
        __syncwarp();

        unsigned qh_base = act_base + 4352 * 4;
        unsigned kh_base = act_base + 6528 * 4;
        unsigned vh_base = act_base + 8704 * 4;
        unsigned hcol_off = (arow * 136 + h * 16 + acol) * 2;

        // ---- scores: q(24x16) @ k^T(16x24), 6 MMAs ----
        unsigned kq0[4], kq1[4], kb0[4], kb1[4];
        ldsm_x4(kq0, qh_base + hcol_off);
        ldsm_x4(kq1, qh_base + hcol_off + 16 * 272);
        ldsm_x4(kb0, kh_base + hcol_off);
        ldsm_x4(kb1, kh_base + hcol_off + 16 * 272);

        float sc[2][3][4] = {};
        mma16816(sc[0][0], kq0, kb0[0], kb0[2]);
        mma16816(sc[0][1], kq0, kb0[1], kb0[3]);
        mma16816(sc[0][2], kq0, kb1[0], kb1[2]);
        mma16816(sc[1][0], kq1, kb0[0], kb0[2]);
        mma16816(sc[1][1], kq1, kb0[1], kb0[3]);
        mma16816(sc[1][2], kq1, kb1[0], kb1[2]);

        // ---- softmax in registers (rows live in 4-lane quads) ----
        int p2 = lane & 3, ql = lane >> 2;
        unsigned ah[3][3];   // [row-group g][col-tile nt] packed half2 probs
        #pragma unroll
        for (int g = 0; g < 3; g++) {
            int t = ql + 8 * g;
            float x[6];
            #pragma unroll
            for (int nt = 0; nt < 3; nt++) {
                #pragma unroll
                for (int p = 0; p < 2; p++) {
                    float raw = (g == 0) ? sc[0][nt][p]
                              : (g == 1) ? sc[0][nt][2 + p]
                                         : sc[1][nt][p];
                    int scol = nt * 8 + 2 * p2 + p;
                    x[nt * 2 + p] = (scol <= t) ? 0.25f * raw : -1e30f;
                }
            }
            float mx = x[0];
            #pragma unroll
            for (int j = 1; j < 6; j++) mx = fmaxf(mx, x[j]);
            mx = fmaxf(mx, __shfl_xor_sync(0xFFFFFFFF, mx, 1));
            mx = fmaxf(mx, __shfl_xor_sync(0xFFFFFFFF, mx, 2));
            float e[6], sum = 0.f;
            #pragma unroll
            for (int j = 0; j < 6; j++) { e[j] = __expf(x[j] - mx); sum += e[j]; }
            sum += __shfl_xor_sync(0xFFFFFFFF, sum, 1);
            sum += __shfl_xor_sync(0xFFFFFFFF, sum, 2);
            float inv = 1.f / sum;
            #pragma unroll
            for (int nt = 0; nt < 3; nt++)
                ah[g][nt] = packh2(e[nt * 2] * inv, e[nt * 2 + 1] * inv);
        }

        // ---- AV: attn(24x24) @ v(24x16), 8 MMAs ----
        unsigned vb0[4], vb1[4];
        ldsm_x4_t(vb0, vh_base + hcol_off);
        ldsm_x4_t(vb1, vh_base + hcol_off + 16 * 272);

        unsigned A00[4] = { ah[0][0], ah[1][0], ah[0][1], ah[1][1] };  // kt s0-15,  rows 0-15
        unsigned A01[4] = { ah[2][0], 0u,       ah[2][1], 0u       };  // kt s0-15,  rows 16-31
        unsigned A10[4] = { ah[0][2], ah[1][2], 0u,       0u       };  // kt s16-31, rows 0-15
        unsigned A11[4] = { ah[2][2], 0u,       0u,       0u       };  // kt s16-31, rows 16-31

        float val[2][2][4] = {};
        #pragma unroll
        for (int ne = 0; ne < 2; ne++) {
            mma16816(val[0][ne], A00, vb0[2 * ne], vb0[2 * ne + 1]);
            mma16816(val[0][ne], A10, vb1[2 * ne], vb1[2 * ne + 1]);
            mma16816(val[1][ne], A01, vb0[2 * ne], vb0[2 * ne + 1]);
            mma16816(val[1][ne], A11, vb1[2 * ne], vb1[2 * ne + 1]);
        }

        // ---- store val (fp32) for epilogue; rows 24-31 discarded ----
        #pragma unroll
        for (int ne = 0; ne < 2; ne++) {
            int colf = h * 16 + ne * 8 + 2 * p2;
            *(float2*)&s_val[ql * PAD + colf]        = make_float2(val[0][ne][0], val[0][ne][1]);
            *(float2*)&s_val[(ql + 8) * PAD + colf]  = make_float2(val[0][ne][2], val[0][ne][3]);
            *(float2*)&s_val[(16 + ql) * PAD + colf] = make_float2(val[1][ne][0], val[1][ne][1]);
        }
    }
    __syncthreads();

    // ---- load gcn under out-proj compute ----
    for (int idx = tid; idx < 1536; idx += 256) s_gcn[idx] = g_gcn[base + idx];

    // ---- value = lrelu(val @ out_w + out_b) ----
    int e0 = (tid & 15) * 4;
    int tg2 = tid >> 4;               // 0..15
    int t0 = tg2, t1 = tg2 + 16;
    int t1c = (t1 < Tc) ? t1 : 0;
    {
        float a0[4] = {}, a1[4] = {};
        #pragma unroll 2
        for (int i = 0; i < 128; i += 4) {
            float4 x0 = *(const float4*)&s_val[t0 * PAD + i];
            float4 x1 = *(const float4*)&s_val[t1c * PAD + i];
            #pragma unroll
            for (int u = 0; u < 4; u++) {
                float4 w4 = *(const float4*)&out_w[(i + u) * 64 + e0];
                float xu0 = (&x0.x)[u], xu1 = (&x1.x)[u];
                a0[0] += xu0 * w4.x; a0[1] += xu0 * w4.y; a0[2] += xu0 * w4.z; a0[3] += xu0 * w4.w;
                a1[0] += xu1 * w4.x; a1[1] += xu1 * w4.y; a1[2] += xu1 * w4.z; a1[3] += xu1 * w4.w;
            }
        }
        float4 ob = *(const float4*)&out_b[e0];
        float4 v0;
        v0.x = lrelu(a0[0] + ob.x); v0.y = lrelu(a0[1] + ob.y);
        v0.z = lrelu(a0[2] + ob.z); v0.w = lrelu(a0[3] + ob.w);
        *(float4*)&s_value[t0 * 64 + e0] = v0;
        if (t1 < Tc) {
            float4 v1;
            v1.x = lrelu(a1[0] + ob.x); v1.y = lrelu(a1[1] + ob.y);
            v1.z = lrelu(a1[2] + ob.z); v1.w = lrelu(a1[3] + ob.w);
            *(float4*)&s_value[t1 * 64 + e0] = v1;
        }
    }
    __syncthreads();

    // ---- gate + blend + residual ----
    {
        float g0[4] = {}, g1[4] = {};
        #pragma unroll 2
        for (int i = 0; i < 64; i += 4) {
            float4 x0 = *(const float4*)&s_gcn[t0 * 64 + i];
            float4 x1 = *(const float4*)&s_gcn[t1c * 64 + i];
            #pragma unroll
            for (int u = 0; u < 4; u++) {
                float4 w4 = *(const float4*)&gate_w[(i + u) * 64 + e0];
                float xu0 = (&x0.x)[u], xu1 = (&x1.x)[u];
                g0[0] += xu0 * w4.x; g0[1] += xu0 * w4.y; g0[2] += xu0 * w4.z; g0[3] += xu0 * w4.w;
                g1[0] += xu1 * w4.x; g1[1] += xu1 * w4.y; g1[2] += xu1 * w4.z; g1[3] += xu1 * w4.w;
            }
        }
        #pragma unroll 2
        for (int i = 0; i < 64; i += 4) {
            float4 x0 = *(const float4*)&s_value[t0 * 64 + i];
            float4 x1 = *(const float4*)&s_value[t1c * 64 + i];
            #pragma unroll
            for (int u = 0; u < 4; u++) {
                float4 w4 = *(const float4*)&gate_w[(64 + i + u) * 64 + e0];
                float xu0 = (&x0.x)[u], xu1 = (&x1.x)[u];
                g0[0] += xu0 * w4.x; g0[1] += xu0 * w4.y; g0[2] += xu0 * w4.z; g0[3] += xu0 * w4.w;
                g1[0] += xu1 * w4.x; g1[1] += xu1 * w4.y; g1[2] += xu1 * w4.z; g1[3] += xu1 * w4.w;
            }
        }
        float4 gb = *(const float4*)&gate_b[e0];
        {
            float4 hd = *(const float4*)&hidden[base + t0 * 64 + e0];
            float zx = 1.f / (1.f + expf(-(g0[0] + gb.x)));
            float zy = 1.f / (1.f + expf(-(g0[1] + gb.y)));
            float zz = 1.f / (1.f + expf(-(g0[2] + gb.z)));
            float zw = 1.f / (1.f + expf(-(g0[3] + gb.w)));
            const float* gc = &s_gcn[t0 * 64 + e0];
            const float* vv = &s_value[t0 * 64 + e0];
            float4 o;
            o.x = zx * gc[0] + (1.f - zx) * vv[0] + hd.x;
            o.y = zy * gc[1] + (1.f - zy) * vv[1] + hd.y;
            o.z = zz * gc[2] + (1.f - zz) * vv[2] + hd.z;
            o.w = zw * gc[3] + (1.f - zw) * vv[3] + hd.w;
            *(float4*)&out[base + t0 * 64 + e0] = o;
        }
        if (t1 < Tc) {
            float4 hd = *(const float4*)&hidden[base + t1 * 64 + e0];
            float zx = 1.f / (1.f + expf(-(g1[0] + gb.x)));
            float zy = 1.f / (1.f + expf(-(g1[1] + gb.y)));
            float zz = 1.f / (1.f + expf(-(g1[2] + gb.z)));
            float zw = 1.f / (1.f + expf(-(g1[3] + gb.w)));
            const float* gc = &s_gcn[t1 * 64 + e0];
            const float* vv = &s_value[t1 * 64 + e0];
            float4 o;
            o.x = zx * gc[0] + (1.f - zx) * vv[0] + hd.x;
            o.y = zy * gc[1] + (1.f - zy) * vv[1] + hd.y;
            o.z = zz * gc[2] + (1.f - zz) * vv[2] + hd.z;
            o.w = zw * gc[3] + (1.f - zw) * vv[3] + hd.w;
            *(float4*)&out[base + t1 * 64 + e0] = o;
        }
    }
}

// ---------------- launch ----------------
extern "C" void kernel_launch(void* const* d_in, const int* in_sizes, int n_in,
                              void* d_out, int out_size) {
    const float* hidden   = (const float*)d_in[0];
    const float* tXin     = (const float*)d_in[1];
    const float* matrix   = (const float*)d_in[2];
    const float* gcn_w    = (const float*)d_in[3];
    const float* gcn_b    = (const float*)d_in[4];
    const float* node_emb = (const float*)d_in[5];
    const float* tproj_w  = (const float*)d_in[6];
    const float* tproj_b  = (const float*)d_in[7];
    const float* WK       = (const float*)d_in[8];
    const float* WQ       = (const float*)d_in[9];
    const float* WV       = (const float*)d_in[10];
    const float* out_w    = (const float*)d_in[11];
    const float* out_b    = (const float*)d_in[12];
    const float* gate_w   = (const float*)d_in[13];
    const float* gate_b   = (const float*)d_in[14];
    float* out = (float*)d_out;

    cudaFuncSetAttribute(k_attn, cudaFuncAttributeMaxDynamicSharedMemorySize, ATTN_SMEM_BYTES);

    k_tfeat<<<Bc, 64>>>(tXin, tproj_w, tproj_b);
    k_gcn<<<dim3(6, Tc, Bc), 256>>>(matrix, hidden, gcn_w, gcn_b);
    k_weff<<<dim3(16, 82, 3), 256>>>(WQ, WK, WV, node_emb);
    k_attn<<<BNc, 256, ATTN_SMEM_BYTES>>>(hidden, tXin, out_w, out_b, gate_w, gate_b, out);
}

// round 10
// speedup vs baseline: 1.4851x; 1.3030x over previous
#include <cuda_runtime.h>
#include <cuda_fp16.h>
#include <math.h>

#define Bc   8
#define Nc   325
#define Tc   24
#define Dc   64
#define Hc   8
#define Mc   16
#define E2c  128
#define BNc  2600   // Bc*Nc
#define PAD  132    // padded row stride for T x E2 fp32 smem tiles

// ---------------- device scratch ----------------
__device__ float g_tfeat[Bc * Mc];                            // (B,16)
__device__ float g_gcn[(size_t)Bc * Nc * Tc * Dc];            // (B,N,T,D) ~16MB
__device__ __align__(16) __half g_weff[(size_t)3 * BNc * E2c * E2c]; // fp16 ~256MB

__device__ __forceinline__ float lrelu(float x) { return x > 0.f ? x : 0.1f * x; }

#define CP_ASYNC16(sdst, gsrc) \
    asm volatile("cp.async.cg.shared.global [%0], [%1], 16;" :: "r"(sdst), "l"(gsrc) : "memory")
#define CP_COMMIT() asm volatile("cp.async.commit_group;" ::: "memory")
#define CP_WAIT1()  asm volatile("cp.async.wait_group 1;" ::: "memory")
#define CP_WAIT0()  asm volatile("cp.async.wait_group 0;" ::: "memory")

__device__ __forceinline__ void ldsm_x4(unsigned* r, unsigned addr) {
    asm volatile("ldmatrix.sync.aligned.m8n8.x4.shared.b16 {%0,%1,%2,%3}, [%4];"
                 : "=r"(r[0]), "=r"(r[1]), "=r"(r[2]), "=r"(r[3]) : "r"(addr));
}
__device__ __forceinline__ void ldsm_x4_t(unsigned* r, unsigned addr) {
    asm volatile("ldmatrix.sync.aligned.m8n8.x4.trans.shared.b16 {%0,%1,%2,%3}, [%4];"
                 : "=r"(r[0]), "=r"(r[1]), "=r"(r[2]), "=r"(r[3]) : "r"(addr));
}
__device__ __forceinline__ void mma16816(float* c, const unsigned* a, unsigned b0, unsigned b1) {
    asm volatile("mma.sync.aligned.m16n8k16.row.col.f32.f16.f16.f32 "
                 "{%0,%1,%2,%3}, {%4,%5,%6,%7}, {%8,%9}, {%0,%1,%2,%3};"
                 : "+f"(c[0]), "+f"(c[1]), "+f"(c[2]), "+f"(c[3])
                 : "r"(a[0]), "r"(a[1]), "r"(a[2]), "r"(a[3]), "r"(b0), "r"(b1));
}
__device__ __forceinline__ unsigned packh2(float a, float b) {
    __half2 h = __floats2half2_rn(a, b);
    return *reinterpret_cast<unsigned*>(&h);
}

// ---------------- Kernel 1: tfeat ----------------
__global__ void k_tfeat(const float* __restrict__ tXin,
                        const float* __restrict__ tpw,
                        const float* __restrict__ tpb) {
    __shared__ float s_mean[Dc];
    int b = blockIdx.x;
    int d = threadIdx.x;  // 64 threads
    const float* p = tXin + (size_t)b * Nc * Tc * Dc;  // n = 0 slice
    float s = 0.f;
    #pragma unroll
    for (int t = 0; t < Tc; t++) s += p[t * Dc + d];
    s_mean[d] = s * (1.0f / Tc);
    __syncthreads();
    if (d < Mc) {
        float acc = tpb[d];
        #pragma unroll
        for (int i = 0; i < Dc; i++) acc += s_mean[i] * tpw[i * Mc + d];
        g_tfeat[b * Mc + d] = tanhf(acc);
    }
}

// ---------------- Kernel 2: support GEMM + GCN, tensor cores --------------------
// support[n,d] = sum_m matrix[b,t,n,m] * hidden[b,m,t,d]; gcn = relu(support@gcn_w + b)
// Block = (nt, t, b): 64 n-rows x 64 d-cols, K=325 (11 chunks of 32).
__global__ __launch_bounds__(256) void k_gcn(const float* __restrict__ matrix,
                                             const float* __restrict__ hidden,
                                             const float* __restrict__ gcn_w,
                                             const float* __restrict__ gcn_b) {
    __shared__ __half sA[64][40];   // matrix chunk: 64 n x 32 k  (80B rows)
    __shared__ __half sB[32][72];   // hidden chunk: 32 k x 64 d  (144B rows)
    __shared__ __half sS[64][72];   // support fp16: 64 n x 64 d
    __shared__ __half sW[64][72];   // gcn_w fp16:   64 d x 64 e
    int tid = threadIdx.x, lane = tid & 31, warp = tid >> 5;
    int nt = blockIdx.x, t = blockIdx.y, b = blockIdx.z;
    int n0 = nt * 64;

    for (int idx = tid; idx < 4096; idx += 256)
        sW[idx >> 6][idx & 63] = __float2half(gcn_w[idx]);

    const float* Mrow = matrix + ((size_t)(b * Tc + t) * Nc) * Nc;

    unsigned sA_b = (unsigned)__cvta_generic_to_shared(&sA[0][0]);
    unsigned sB_b = (unsigned)__cvta_generic_to_shared(&sB[0][0]);
    unsigned sS_b = (unsigned)__cvta_generic_to_shared(&sS[0][0]);
    unsigned sW_b = (unsigned)__cvta_generic_to_shared(&sW[0][0]);

    int r0 = (warp >> 1) * 16;      // warp row block (n)
    int c0 = (warp & 1) * 32;       // warp col block (d or e)
    int arow = (lane & 7) + (lane & 8);
    int acol8 = (lane & 16) ? 8 : 0;
    int trow = lane >> 2, p2 = lane & 3;

    float acc[4][4] = {};
    for (int kc = 0; kc < 11; kc++) {
        int m0 = kc * 32;
        __syncthreads();   // protect sA/sB overwrite vs previous compute
        for (int idx = tid; idx < 2048; idx += 256) {
            int i = idx >> 5, j = idx & 31;
            int n = n0 + i, m = m0 + j;
            float v = (n < Nc && m < Nc) ? Mrow[(size_t)n * Nc + m] : 0.f;
            sA[i][j] = __float2half(v);
        }
        for (int idx = tid; idx < 2048; idx += 256) {
            int j = idx >> 6, d = idx & 63;
            int m = m0 + j;
            float v = (m < Nc) ? hidden[((size_t)(b * Nc + m) * Tc + t) * Dc + d] : 0.f;
            sB[j][d] = __float2half(v);
        }
        __syncthreads();
        #pragma unroll
        for (int ks = 0; ks < 2; ks++) {
            unsigned af[4], bf0[4], bf1[4];
            ldsm_x4(af,    sA_b + ((r0 + arow) * 40 + ks * 16 + acol8) * 2);
            ldsm_x4_t(bf0, sB_b + ((ks * 16 + arow) * 72 + c0 + acol8) * 2);
            ldsm_x4_t(bf1, sB_b + ((ks * 16 + arow) * 72 + c0 + 16 + acol8) * 2);
            mma16816(acc[0], af, bf0[0], bf0[1]);
            mma16816(acc[1], af, bf0[2], bf0[3]);
            mma16816(acc[2], af, bf1[0], bf1[1]);
            mma16816(acc[3], af, bf1[2], bf1[3]);
        }
    }

    // store support fragments (fp16) to sS
    #pragma unroll
    for (int ntile = 0; ntile < 4; ntile++) {
        int col = c0 + ntile * 8 + 2 * p2;
        *(__half2*)&sS[r0 + trow][col]     = __floats2half2_rn(acc[ntile][0], acc[ntile][1]);
        *(__half2*)&sS[r0 + trow + 8][col] = __floats2half2_rn(acc[ntile][2], acc[ntile][3]);
    }
    __syncthreads();

    // second GEMM: gcn = relu(support @ gcn_w + b), K=64
    float acc2[4][4] = {};
    #pragma unroll
    for (int ks = 0; ks < 4; ks++) {
        unsigned af[4], bf0[4], bf1[4];
        ldsm_x4(af,    sS_b + ((r0 + arow) * 72 + ks * 16 + acol8) * 2);
        ldsm_x4_t(bf0, sW_b + ((ks * 16 + arow) * 72 + c0 + acol8) * 2);
        ldsm_x4_t(bf1, sW_b + ((ks * 16 + arow) * 72 + c0 + 16 + acol8) * 2);
        mma16816(acc2[0], af, bf0[0], bf0[1]);
        mma16816(acc2[1], af, bf0[2], bf0[3]);
        mma16816(acc2[2], af, bf1[0], bf1[1]);
        mma16816(acc2[3], af, bf1[2], bf1[3]);
    }

    // bias + relu + fp32 store (guard n < Nc)
    #pragma unroll
    for (int ntile = 0; ntile < 4; ntile++) {
        int col = c0 + ntile * 8 + 2 * p2;
        float bx = gcn_b[col], by = gcn_b[col + 1];
        int n1 = n0 + r0 + trow, n2 = n1 + 8;
        if (n1 < Nc) {
            float2 o = make_float2(fmaxf(acc2[ntile][0] + bx, 0.f),
                                   fmaxf(acc2[ntile][1] + by, 0.f));
            *(float2*)&g_gcn[((size_t)(b * Nc + n1) * Tc + t) * Dc + col] = o;
        }
        if (n2 < Nc) {
            float2 o = make_float2(fmaxf(acc2[ntile][2] + bx, 0.f),
                                   fmaxf(acc2[ntile][3] + by, 0.f));
            *(float2*)&g_gcn[((size_t)(b * Nc + n2) * Tc + t) * Dc + col] = o;
        }
    }
}

// ---------------- Kernel 3: Weff build (fp16 out), W in regs, 32 rows/block -----
__global__ __launch_bounds__(256) void k_weff(const float* __restrict__ WQ,
                                              const float* __restrict__ WK,
                                              const float* __restrict__ WV,
                                              const float* __restrict__ node_emb) {
    __shared__ float s_emb[32][16];
    int tid = threadIdx.x;
    int cx = blockIdx.x;   // 16 chunks of 1024 cols
    int by = blockIdx.y;   // 82 groups of 32 bn rows
    int X  = blockIdx.z;   // 0=Q,1=K,2=V
    const float* W = (X == 0) ? WQ : (X == 1) ? WK : WV;
    int c0 = cx * 1024 + tid * 4;

    float4 w[16];
    #pragma unroll
    for (int m = 0; m < 16; m++) w[m] = *(const float4*)&W[(size_t)m * 16384 + c0];

    for (int idx = tid; idx < 512; idx += 256) {
        int row = idx >> 4, m = idx & 15;
        int bn = by * 32 + row;
        if (bn < BNc) {
            int b = bn / Nc, n = bn - b * Nc;
            s_emb[row][m] = node_emb[n * Mc + m] * g_tfeat[b * Mc + m];
        }
    }
    __syncthreads();

    #pragma unroll 4
    for (int row = 0; row < 32; row++) {
        int bn = by * 32 + row;
        if (bn >= BNc) break;
        float4 acc = make_float4(0.f, 0.f, 0.f, 0.f);
        #pragma unroll
        for (int m = 0; m < 16; m++) {
            float e = s_emb[row][m];
            acc.x += e * w[m].x; acc.y += e * w[m].y;
            acc.z += e * w[m].z; acc.w += e * w[m].w;
        }
        __half2 h0 = __floats2half2_rn(acc.x, acc.y);
        __half2 h1 = __floats2half2_rn(acc.z, acc.w);
        __half2* dst = (__half2*)&g_weff[((size_t)X * BNc + bn) * 16384 + c0];
        dst[0] = h0; dst[1] = h1;
    }
}

// ---------------- Kernel 4: fused per-(b,n) attention path (round-8, passing) ---
#define ATTN_SMEM_FLOATS 13952
#define ATTN_SMEM_BYTES  (ATTN_SMEM_FLOATS * 4)

__global__ __launch_bounds__(256, 4) void k_attn(const float* __restrict__ hidden,
                                                 const float* __restrict__ tXin,
                                                 const float* __restrict__ out_w,
                                                 const float* __restrict__ out_b,
                                                 const float* __restrict__ gate_w,
                                                 const float* __restrict__ gate_b,
                                                 float* __restrict__ out) {
    extern __shared__ float sm[];
    __half* s_act  = (__half*)sm;              // 32x136 halfs
    __half* s_qh   = (__half*)(sm + 4352);
    __half* s_kh   = (__half*)(sm + 6528);
    __half* s_vh   = (__half*)(sm + 8704);
    float* s_val   = sm;                       // fp32 24xPAD overlay
    float* s_value = sm + 10880;               // 24x64
    float* s_gcn   = sm + 12416;               // 24x64

    int tid  = threadIdx.x;
    int lane = tid & 31;
    int warp = tid >> 5;
    int bn   = blockIdx.x;
    size_t base = (size_t)bn * (Tc * Dc);

    for (int idx = tid; idx < 4096; idx += 256) {
        int t = idx >> 7, i = idx & 127;
        float vv = 0.f;
        if (t < Tc) vv = (i < 64) ? hidden[base + t * 64 + i] : tXin[base + t * 64 + (i - 64)];
        s_act[t * 136 + i] = __float2half(vv);
    }

    const __half* wq = g_weff + (size_t)bn * 16384;
    const __half* wk = g_weff + ((size_t)BNc + bn) * 16384;
    const __half* wv = g_weff + ((size_t)2 * BNc + bn) * 16384;

    unsigned act_base = (unsigned)__cvta_generic_to_shared(s_act);
    unsigned w_base   = act_base + 8704;

    int srow = tid >> 4, sseg = tid & 15;
    unsigned sdst_off = srow * 272 + sseg * 16;
    int ssrc_off = srow * 128 + sseg * 8;

    CP_ASYNC16(w_base + sdst_off, wq + ssrc_off);
    CP_COMMIT();

    int arow = (lane & 7) + (lane & 8);
    int acol = (lane & 16) ? 8 : 0;
    unsigned a_off0 = (arow * 136 + acol) * 2;
    unsigned a_off1 = ((16 + arow) * 136 + acol) * 2;
    int wn = warp * 16;
    unsigned b_off = (arow * 136 + wn + acol) * 2;

    int trow = lane >> 2, tcol = (lane & 3) * 2;

    int buf = 0;
    for (int X = 0; X < 3; X++) {
        float acc[2][2][4] = {};
        for (int kk = 0; kk < 8; kk++) {
            int s = X * 8 + kk;
            if (s < 23) {
                int s1 = s + 1;
                int X1 = s1 >> 3, i0 = (s1 & 7) * 16;
                const __half* w = (X1 == 0) ? wq : (X1 == 1) ? wk : wv;
                CP_ASYNC16(w_base + (buf ^ 1) * 4352 + sdst_off, w + i0 * 128 + ssrc_off);
                CP_COMMIT();
                CP_WAIT1();
            } else {
                CP_WAIT0();
            }
            __syncthreads();

            unsigned a0f[4], a1f[4], bf[4];
            ldsm_x4(a0f, act_base + a_off0 + kk * 32);
            ldsm_x4(a1f, act_base + a_off1 + kk * 32);
            ldsm_x4_t(bf, w_base + buf * 4352 + b_off);
            mma16816(acc[0][0], a0f, bf[0], bf[1]);
            mma16816(acc[0][1], a1f, bf[0], bf[1]);
            mma16816(acc[1][0], a0f, bf[2], bf[3]);
            mma16816(acc[1][1], a1f, bf[2], bf[3]);

            __syncthreads();
            buf ^= 1;
        }
        __half* dst = (X == 0) ? s_qh : (X == 1) ? s_kh : s_vh;
        #pragma unroll
        for (int nt = 0; nt < 2; nt++) {
            int colb = wn + nt * 8 + tcol;
            float* c0p = acc[nt][0];
            *(__half2*)&dst[trow * 136 + colb] = __floats2half2_rn(lrelu(c0p[0]), lrelu(c0p[1]));
            *(__half2*)&dst[(trow + 8) * 136 + colb] = __floats2half2_rn(lrelu(c0p[2]), lrelu(c0p[3]));
            float* c1p = acc[nt][1];
            *(__half2*)&dst[(16 + trow) * 136 + colb] = __floats2half2_rn(lrelu(c1p[0]), lrelu(c1p[1]));
        }
    }

    // ================= warp-local attention: head h = warp ======================
    {
        int h = warp;
        {
            int r = 24 + (lane >> 2);
            int cu = (lane & 3) * 2;
            unsigned* vz = (unsigned*)s_vh;
            vz[r * 68 + h * 8 + cu]     = 0u;
            vz[r * 68 + h * 8 + cu + 1] = 0u;
        }
        __syncwarp();

        unsigned qh_base = act_base + 4352 * 4;
        unsigned kh_base = act_base + 6528 * 4;
        unsigned vh_base = act_base + 8704 * 4;
        unsigned hcol_off = (arow * 136 + h * 16 + acol) * 2;

        unsigned kq0[4], kq1[4], kb0[4], kb1[4];
        ldsm_x4(kq0, qh_base + hcol_off);
        ldsm_x4(kq1, qh_base + hcol_off + 16 * 272);
        ldsm_x4(kb0, kh_base + hcol_off);
        ldsm_x4(kb1, kh_base + hcol_off + 16 * 272);

        float sc[2][3][4] = {};
        mma16816(sc[0][0], kq0, kb0[0], kb0[2]);
        mma16816(sc[0][1], kq0, kb0[1], kb0[3]);
        mma16816(sc[0][2], kq0, kb1[0], kb1[2]);
        mma16816(sc[1][0], kq1, kb0[0], kb0[2]);
        mma16816(sc[1][1], kq1, kb0[1], kb0[3]);
        mma16816(sc[1][2], kq1, kb1[0], kb1[2]);

        int p2 = lane & 3, ql = lane >> 2;
        unsigned ah[3][3];
        #pragma unroll
        for (int g = 0; g < 3; g++) {
            int t = ql + 8 * g;
            float x[6];
            #pragma unroll
            for (int nt = 0; nt < 3; nt++) {
                #pragma unroll
                for (int p = 0; p < 2; p++) {
                    float raw = (g == 0) ? sc[0][nt][p]
                              : (g == 1) ? sc[0][nt][2 + p]
                                         : sc[1][nt][p];
                    int scol = nt * 8 + 2 * p2 + p;
                    x[nt * 2 + p] = (scol <= t) ? 0.25f * raw : -1e30f;
                }
            }
            float mx = x[0];
            #pragma unroll
            for (int j = 1; j < 6; j++) mx = fmaxf(mx, x[j]);
            mx = fmaxf(mx, __shfl_xor_sync(0xFFFFFFFF, mx, 1));
            mx = fmaxf(mx, __shfl_xor_sync(0xFFFFFFFF, mx, 2));
            float e[6], sum = 0.f;
            #pragma unroll
            for (int j = 0; j < 6; j++) { e[j] = __expf(x[j] - mx); sum += e[j]; }
            sum += __shfl_xor_sync(0xFFFFFFFF, sum, 1);
            sum += __shfl_xor_sync(0xFFFFFFFF, sum, 2);
            float inv = 1.f / sum;
            #pragma unroll
            for (int nt = 0; nt < 3; nt++)
                ah[g][nt] = packh2(e[nt * 2] * inv, e[nt * 2 + 1] * inv);
        }

        unsigned vb0[4], vb1[4];
        ldsm_x4_t(vb0, vh_base + hcol_off);
        ldsm_x4_t(vb1, vh_base + hcol_off + 16 * 272);

        unsigned A00[4] = { ah[0][0], ah[1][0], ah[0][1], ah[1][1] };
        unsigned A01[4] = { ah[2][0], 0u,       ah[2][1], 0u       };
        unsigned A10[4] = { ah[0][2], ah[1][2], 0u,       0u       };
        unsigned A11[4] = { ah[2][2], 0u,       0u,       0u       };

        float val[2][2][4] = {};
        #pragma unroll
        for (int ne = 0; ne < 2; ne++) {
            mma16816(val[0][ne], A00, vb0[2 * ne], vb0[2 * ne + 1]);
            mma16816(val[0][ne], A10, vb1[2 * ne], vb1[2 * ne + 1]);
            mma16816(val[1][ne], A01, vb0[2 * ne], vb0[2 * ne + 1]);
            mma16816(val[1][ne], A11, vb1[2 * ne], vb1[2 * ne + 1]);
        }

        #pragma unroll
        for (int ne = 0; ne < 2; ne++) {
            int colf = h * 16 + ne * 8 + 2 * p2;
            *(float2*)&s_val[ql * PAD + colf]        = make_float2(val[0][ne][0], val[0][ne][1]);
            *(float2*)&s_val[(ql + 8) * PAD + colf]  = make_float2(val[0][ne][2], val[0][ne][3]);
            *(float2*)&s_val[(16 + ql) * PAD + colf] = make_float2(val[1][ne][0], val[1][ne][1]);
        }
    }
    __syncthreads();

    for (int idx = tid; idx < 1536; idx += 256) s_gcn[idx] = g_gcn[base + idx];

    int e0 = (tid & 15) * 4;
    int tg2 = tid >> 4;
    int t0 = tg2, t1 = tg2 + 16;
    int t1c = (t1 < Tc) ? t1 : 0;
    {
        float a0[4] = {}, a1[4] = {};
        #pragma unroll 2
        for (int i = 0; i < 128; i += 4) {
            float4 x0 = *(const float4*)&s_val[t0 * PAD + i];
            float4 x1 = *(const float4*)&s_val[t1c * PAD + i];
            #pragma unroll
            for (int u = 0; u < 4; u++) {
                float4 w4 = *(const float4*)&out_w[(i + u) * 64 + e0];
                float xu0 = (&x0.x)[u], xu1 = (&x1.x)[u];
                a0[0] += xu0 * w4.x; a0[1] += xu0 * w4.y; a0[2] += xu0 * w4.z; a0[3] += xu0 * w4.w;
                a1[0] += xu1 * w4.x; a1[1] += xu1 * w4.y; a1[2] += xu1 * w4.z; a1[3] += xu1 * w4.w;
            }
        }
        float4 ob = *(const float4*)&out_b[e0];
        float4 v0;
        v0.x = lrelu(a0[0] + ob.x); v0.y = lrelu(a0[1] + ob.y);
        v0.z = lrelu(a0[2] + ob.z); v0.w = lrelu(a0[3] + ob.w);
        *(float4*)&s_value[t0 * 64 + e0] = v0;
        if (t1 < Tc) {
            float4 v1;
            v1.x = lrelu(a1[0] + ob.x); v1.y = lrelu(a1[1] + ob.y);
            v1.z = lrelu(a1[2] + ob.z); v1.w = lrelu(a1[3] + ob.w);
            *(float4*)&s_value[t1 * 64 + e0] = v1;
        }
    }
    __syncthreads();

    {
        float g0[4] = {}, g1[4] = {};
        #pragma unroll 2
        for (int i = 0; i < 64; i += 4) {
            float4 x0 = *(const float4*)&s_gcn[t0 * 64 + i];
            float4 x1 = *(const float4*)&s_gcn[t1c * 64 + i];
            #pragma unroll
            for (int u = 0; u < 4; u++) {
                float4 w4 = *(const float4*)&gate_w[(i + u) * 64 + e0];
                float xu0 = (&x0.x)[u], xu1 = (&x1.x)[u];
                g0[0] += xu0 * w4.x; g0[1] += xu0 * w4.y; g0[2] += xu0 * w4.z; g0[3] += xu0 * w4.w;
                g1[0] += xu1 * w4.x; g1[1] += xu1 * w4.y; g1[2] += xu1 * w4.z; g1[3] += xu1 * w4.w;
            }
        }
        #pragma unroll 2
        for (int i = 0; i < 64; i += 4) {
            float4 x0 = *(const float4*)&s_value[t0 * 64 + i];
            float4 x1 = *(const float4*)&s_value[t1c * 64 + i];
            #pragma unroll
            for (int u = 0; u < 4; u++) {
                float4 w4 = *(const float4*)&gate_w[(64 + i + u) * 64 + e0];
                float xu0 = (&x0.x)[u], xu1 = (&x1.x)[u];
                g0[0] += xu0 * w4.x; g0[1] += xu0 * w4.y; g0[2] += xu0 * w4.z; g0[3] += xu0 * w4.w;
                g1[0] += xu1 * w4.x; g1[1] += xu1 * w4.y; g1[2] += xu1 * w4.z; g1[3] += xu1 * w4.w;
            }
        }
        float4 gb = *(const float4*)&gate_b[e0];
        {
            float4 hd = *(const float4*)&hidden[base + t0 * 64 + e0];
            float zx = 1.f / (1.f + expf(-(g0[0] + gb.x)));
            float zy = 1.f / (1.f + expf(-(g0[1] + gb.y)));
            float zz = 1.f / (1.f + expf(-(g0[2] + gb.z)));
            float zw = 1.f / (1.f + expf(-(g0[3] + gb.w)));
            const float* gc = &s_gcn[t0 * 64 + e0];
            const float* vv = &s_value[t0 * 64 + e0];
            float4 o;
            o.x = zx * gc[0] + (1.f - zx) * vv[0] + hd.x;
            o.y = zy * gc[1] + (1.f - zy) * vv[1] + hd.y;
            o.z = zz * gc[2] + (1.f - zz) * vv[2] + hd.z;
            o.w = zw * gc[3] + (1.f - zw) * vv[3] + hd.w;
            *(float4*)&out[base + t0 * 64 + e0] = o;
        }
        if (t1 < Tc) {
            float4 hd = *(const float4*)&hidden[base + t1 * 64 + e0];
            float zx = 1.f / (1.f + expf(-(g1[0] + gb.x)));
            float zy = 1.f / (1.f + expf(-(g1[1] + gb.y)));
            float zz = 1.f / (1.f + expf(-(g1[2] + gb.z)));
            float zw = 1.f / (1.f + expf(-(g1[3] + gb.w)));
            const float* gc = &s_gcn[t1 * 64 + e0];
            const float* vv = &s_value[t1 * 64 + e0];
            float4 o;
            o.x = zx * gc[0] + (1.f - zx) * vv[0] + hd.x;
            o.y = zy * gc[1] + (1.f - zy) * vv[1] + hd.y;
            o.z = zz * gc[2] + (1.f - zz) * vv[2] + hd.z;
            o.w = zw * gc[3] + (1.f - zw) * vv[3] + hd.w;
            *(float4*)&out[base + t1 * 64 + e0] = o;
        }
    }
}

// ---------------- launch ----------------
extern "C" void kernel_launch(void* const* d_in, const int* in_sizes, int n_in,
                              void* d_out, int out_size) {
    const float* hidden   = (const float*)d_in[0];
    const float* tXin     = (const float*)d_in[1];
    const float* matrix   = (const float*)d_in[2];
    const float* gcn_w    = (const float*)d_in[3];
    const float* gcn_b    = (const float*)d_in[4];
    const float* node_emb = (const float*)d_in[5];
    const float* tproj_w  = (const float*)d_in[6];
    const float* tproj_b  = (const float*)d_in[7];
    const float* WK       = (const float*)d_in[8];
    const float* WQ       = (const float*)d_in[9];
    const float* WV       = (const float*)d_in[10];
    const float* out_w    = (const float*)d_in[11];
    const float* out_b    = (const float*)d_in[12];
    const float* gate_w   = (const float*)d_in[13];
    const float* gate_b   = (const float*)d_in[14];
    float* out = (float*)d_out;

    cudaFuncSetAttribute(k_attn, cudaFuncAttributeMaxDynamicSharedMemorySize, ATTN_SMEM_BYTES);

    k_tfeat<<<Bc, 64>>>(tXin, tproj_w, tproj_b);
    k_gcn<<<dim3(6, Tc, Bc), 256>>>(matrix, hidden, gcn_w, gcn_b);
    k_weff<<<dim3(16, 82, 3), 256>>>(WQ, WK, WV, node_emb);
    k_attn<<<BNc, 256, ATTN_SMEM_BYTES>>>(hidden, tXin, out_w, out_b, gate_w, gate_b, out);
}

// round 13
// speedup vs baseline: 1.4860x; 1.0006x over previous
#include <cuda_runtime.h>
#include <cuda_fp16.h>
#include <math.h>

#define Bc   8
#define Nc   325
#define Tc   24
#define Dc   64
#define Hc   8
#define Mc   16
#define E2c  128
#define BNc  2600   // Bc*Nc
#define PAD  132    // padded row stride for T x E2 fp32 smem tiles

// ---------------- device scratch ----------------
__device__ float g_tfeat[Bc * Mc];                            // (B,16)
__device__ float g_gcn[(size_t)Bc * Nc * Tc * Dc];            // (B,N,T,D) ~16MB
__device__ __align__(16) __half g_weff[(size_t)3 * BNc * E2c * E2c]; // fp16 ~256MB

__device__ __forceinline__ float lrelu(float x) { return x > 0.f ? x : 0.1f * x; }

#define CP_ASYNC16(sdst, gsrc) \
    asm volatile("cp.async.cg.shared.global [%0], [%1], 16;" :: "r"(sdst), "l"(gsrc) : "memory")
#define CP_COMMIT() asm volatile("cp.async.commit_group;" ::: "memory")
#define CP_WAIT1()  asm volatile("cp.async.wait_group 1;" ::: "memory")
#define CP_WAIT0()  asm volatile("cp.async.wait_group 0;" ::: "memory")

__device__ __forceinline__ void ldsm_x4(unsigned* r, unsigned addr) {
    asm volatile("ldmatrix.sync.aligned.m8n8.x4.shared.b16 {%0,%1,%2,%3}, [%4];"
                 : "=r"(r[0]), "=r"(r[1]), "=r"(r[2]), "=r"(r[3]) : "r"(addr));
}
__device__ __forceinline__ void ldsm_x4_t(unsigned* r, unsigned addr) {
    asm volatile("ldmatrix.sync.aligned.m8n8.x4.trans.shared.b16 {%0,%1,%2,%3}, [%4];"
                 : "=r"(r[0]), "=r"(r[1]), "=r"(r[2]), "=r"(r[3]) : "r"(addr));
}
__device__ __forceinline__ void mma16816(float* c, const unsigned* a, unsigned b0, unsigned b1) {
    asm volatile("mma.sync.aligned.m16n8k16.row.col.f32.f16.f16.f32 "
                 "{%0,%1,%2,%3}, {%4,%5,%6,%7}, {%8,%9}, {%0,%1,%2,%3};"
                 : "+f"(c[0]), "+f"(c[1]), "+f"(c[2]), "+f"(c[3])
                 : "r"(a[0]), "r"(a[1]), "r"(a[2]), "r"(a[3]), "r"(b0), "r"(b1));
}
__device__ __forceinline__ unsigned packh2(float a, float b) {
    __half2 h = __floats2half2_rn(a, b);
    return *reinterpret_cast<unsigned*>(&h);
}

// ---------------- Kernel 1: tfeat ----------------
__global__ void k_tfeat(const float* __restrict__ tXin,
                        const float* __restrict__ tpw,
                        const float* __restrict__ tpb) {
    __shared__ float s_mean[Dc];
    int b = blockIdx.x;
    int d = threadIdx.x;  // 64 threads
    const float* p = tXin + (size_t)b * Nc * Tc * Dc;  // n = 0 slice
    float s = 0.f;
    #pragma unroll
    for (int t = 0; t < Tc; t++) s += p[t * Dc + d];
    s_mean[d] = s * (1.0f / Tc);
    __syncthreads();
    if (d < Mc) {
        float acc = tpb[d];
        #pragma unroll
        for (int i = 0; i < Dc; i++) acc += s_mean[i] * tpw[i * Mc + d];
        g_tfeat[b * Mc + d] = tanhf(acc);
    }
}

// ---------------- Kernel 2: support GEMM + GCN, tensor cores --------------------
__global__ __launch_bounds__(256) void k_gcn(const float* __restrict__ matrix,
                                             const float* __restrict__ hidden,
                                             const float* __restrict__ gcn_w,
                                             const float* __restrict__ gcn_b) {
    __shared__ __half sA[64][40];   // matrix chunk: 64 n x 32 k  (80B rows)
    __shared__ __half sB[32][72];   // hidden chunk: 32 k x 64 d  (144B rows)
    __shared__ __half sS[64][72];   // support fp16: 64 n x 64 d
    __shared__ __half sW[64][72];   // gcn_w fp16:   64 d x 64 e
    int tid = threadIdx.x, lane = tid & 31, warp = tid >> 5;
    int nt = blockIdx.x, t = blockIdx.y, b = blockIdx.z;
    int n0 = nt * 64;

    for (int idx = tid; idx < 4096; idx += 256)
        sW[idx >> 6][idx & 63] = __float2half(gcn_w[idx]);

    const float* Mrow = matrix + ((size_t)(b * Tc + t) * Nc) * Nc;

    unsigned sA_b = (unsigned)__cvta_generic_to_shared(&sA[0][0]);
    unsigned sB_b = (unsigned)__cvta_generic_to_shared(&sB[0][0]);
    unsigned sS_b = (unsigned)__cvta_generic_to_shared(&sS[0][0]);
    unsigned sW_b = (unsigned)__cvta_generic_to_shared(&sW[0][0]);

    int r0 = (warp >> 1) * 16;      // warp row block (n)
    int c0 = (warp & 1) * 32;       // warp col block (d or e)
    int arow = (lane & 7) + (lane & 8);
    int acol8 = (lane & 16) ? 8 : 0;
    int trow = lane >> 2, p2 = lane & 3;

    float acc[4][4] = {};
    for (int kc = 0; kc < 11; kc++) {
        int m0 = kc * 32;
        __syncthreads();   // protect sA/sB overwrite vs previous compute
        for (int idx = tid; idx < 2048; idx += 256) {
            int i = idx >> 5, j = idx & 31;
            int n = n0 + i, m = m0 + j;
            float v = (n < Nc && m < Nc) ? Mrow[(size_t)n * Nc + m] : 0.f;
            sA[i][j] = __float2half(v);
        }
        for (int idx = tid; idx < 2048; idx += 256) {
            int j = idx >> 6, d = idx & 63;
            int m = m0 + j;
            float v = (m < Nc) ? hidden[((size_t)(b * Nc + m) * Tc + t) * Dc + d] : 0.f;
            sB[j][d] = __float2half(v);
        }
        __syncthreads();
        #pragma unroll
        for (int ks = 0; ks < 2; ks++) {
            unsigned af[4], bf0[4], bf1[4];
            ldsm_x4(af,    sA_b + ((r0 + arow) * 40 + ks * 16 + acol8) * 2);
            ldsm_x4_t(bf0, sB_b + ((ks * 16 + arow) * 72 + c0 + acol8) * 2);
            ldsm_x4_t(bf1, sB_b + ((ks * 16 + arow) * 72 + c0 + 16 + acol8) * 2);
            mma16816(acc[0], af, bf0[0], bf0[1]);
            mma16816(acc[1], af, bf0[2], bf0[3]);
            mma16816(acc[2], af, bf1[0], bf1[1]);
            mma16816(acc[3], af, bf1[2], bf1[3]);
        }
    }

    // store support fragments (fp16) to sS
    #pragma unroll
    for (int ntile = 0; ntile < 4; ntile++) {
        int col = c0 + ntile * 8 + 2 * p2;
        *(__half2*)&sS[r0 + trow][col]     = __floats2half2_rn(acc[ntile][0], acc[ntile][1]);
        *(__half2*)&sS[r0 + trow + 8][col] = __floats2half2_rn(acc[ntile][2], acc[ntile][3]);
    }
    __syncthreads();

    // second GEMM: gcn = relu(support @ gcn_w + b), K=64
    float acc2[4][4] = {};
    #pragma unroll
    for (int ks = 0; ks < 4; ks++) {
        unsigned af[4], bf0[4], bf1[4];
        ldsm_x4(af,    sS_b + ((r0 + arow) * 72 + ks * 16 + acol8) * 2);
        ldsm_x4_t(bf0, sW_b + ((ks * 16 + arow) * 72 + c0 + acol8) * 2);
        ldsm_x4_t(bf1, sW_b + ((ks * 16 + arow) * 72 + c0 + 16 + acol8) * 2);
        mma16816(acc2[0], af, bf0[0], bf0[1]);
        mma16816(acc2[1], af, bf0[2], bf0[3]);
        mma16816(acc2[2], af, bf1[0], bf1[1]);
        mma16816(acc2[3], af, bf1[2], bf1[3]);
    }

    // bias + relu + fp32 store (guard n < Nc)
    #pragma unroll
    for (int ntile = 0; ntile < 4; ntile++) {
        int col = c0 + ntile * 8 + 2 * p2;
        float bx = gcn_b[col], by = gcn_b[col + 1];
        int n1 = n0 + r0 + trow, n2 = n1 + 8;
        if (n1 < Nc) {
            float2 o = make_float2(fmaxf(acc2[ntile][0] + bx, 0.f),
                                   fmaxf(acc2[ntile][1] + by, 0.f));
            *(float2*)&g_gcn[((size_t)(b * Nc + n1) * Tc + t) * Dc + col] = o;
        }
        if (n2 < Nc) {
            float2 o = make_float2(fmaxf(acc2[ntile][2] + bx, 0.f),
                                   fmaxf(acc2[ntile][3] + by, 0.f));
            *(float2*)&g_gcn[((size_t)(b * Nc + n2) * Tc + t) * Dc + col] = o;
        }
    }
}

// ---------------- Kernel 3: Weff build (fp16 out), W in regs, 32 rows/block -----
__global__ __launch_bounds__(256) void k_weff(const float* __restrict__ WQ,
                                              const float* __restrict__ WK,
                                              const float* __restrict__ WV,
                                              const float* __restrict__ node_emb) {
    __shared__ float s_emb[32][16];
    int tid = threadIdx.x;
    int cx = blockIdx.x;   // 16 chunks of 1024 cols
    int by = blockIdx.y;   // 82 groups of 32 bn rows
    int X  = blockIdx.z;   // 0=Q,1=K,2=V
    const float* W = (X == 0) ? WQ : (X == 1) ? WK : WV;
    int c0 = cx * 1024 + tid * 4;

    float4 w[16];
    #pragma unroll
    for (int m = 0; m < 16; m++) w[m] = *(const float4*)&W[(size_t)m * 16384 + c0];

    for (int idx = tid; idx < 512; idx += 256) {
        int row = idx >> 4, m = idx & 15;
        int bn = by * 32 + row;
        if (bn < BNc) {
            int b = bn / Nc, n = bn - b * Nc;
            s_emb[row][m] = node_emb[n * Mc + m] * g_tfeat[b * Mc + m];
        }
    }
    __syncthreads();

    #pragma unroll 4
    for (int row = 0; row < 32; row++) {
        int bn = by * 32 + row;
        if (bn >= BNc) break;
        float4 acc = make_float4(0.f, 0.f, 0.f, 0.f);
        #pragma unroll
        for (int m = 0; m < 16; m++) {
            float e = s_emb[row][m];
            acc.x += e * w[m].x; acc.y += e * w[m].y;
            acc.z += e * w[m].z; acc.w += e * w[m].w;
        }
        __half2 h0 = __floats2half2_rn(acc.x, acc.y);
        __half2 h1 = __floats2half2_rn(acc.z, acc.w);
        __half2* dst = (__half2*)&g_weff[((size_t)X * BNc + bn) * 16384 + c0];
        dst[0] = h0; dst[1] = h1;
    }
}

// ---------------- Kernel 4: fused per-(b,n) attention path ----------------------
// smem (float units), total 13824 floats = 55296B (4 CTAs/SM):
//   [0, 2176)      s_act fp16 32x136          | s_val fp32 24xPAD overlay [0,3168)
//   [2176, 4224)   s_wp: per-warp weight slabs, 8 warps x 2 bufs x 512B
//   [4224, 6400)   s_qh fp16 32x136
//   [6400, 8576)   s_kh fp16 32x136
//   [8576, 10752)  s_vh fp16 32x136
//   [10752, 12288) s_value fp32 24x64
//   [12288, 13824) s_gcn  fp32 24x64
// NOTE: s_val overlays s_act AND the warp weight slabs -> a block barrier is
// REQUIRED between the (warp-drifting) proj mainloop and any s_val store.
#define ATTN_SMEM_FLOATS 13824
#define ATTN_SMEM_BYTES  (ATTN_SMEM_FLOATS * 4)

__global__ __launch_bounds__(256, 4) void k_attn(const float* __restrict__ hidden,
                                                 const float* __restrict__ tXin,
                                                 const float* __restrict__ out_w,
                                                 const float* __restrict__ out_b,
                                                 const float* __restrict__ gate_w,
                                                 const float* __restrict__ gate_b,
                                                 float* __restrict__ out) {
    extern __shared__ float sm[];
    __half* s_act  = (__half*)sm;              // 32x136 halfs
    __half* s_qh   = (__half*)(sm + 4224);
    __half* s_kh   = (__half*)(sm + 6400);
    __half* s_vh   = (__half*)(sm + 8576);
    float* s_val   = sm;                       // fp32 24xPAD overlay (proj area dead)
    float* s_value = sm + 10752;               // 24x64
    float* s_gcn   = sm + 12288;               // 24x64

    int tid  = threadIdx.x;
    int lane = tid & 31;
    int warp = tid >> 5;
    int bn   = blockIdx.x;
    size_t base = (size_t)bn * (Tc * Dc);

    // ---- stage activations as fp16 (rows 24-31 zero) ----
    for (int idx = tid; idx < 4096; idx += 256) {
        int t = idx >> 7, i = idx & 127;
        float vv = 0.f;
        if (t < Tc) vv = (i < 64) ? hidden[base + t * 64 + i] : tXin[base + t * 64 + (i - 64)];
        s_act[t * 136 + i] = __float2half(vv);
    }

    const __half* wq = g_weff + (size_t)bn * 16384;
    const __half* wk = g_weff + ((size_t)BNc + bn) * 16384;
    const __half* wv = g_weff + ((size_t)2 * BNc + bn) * 16384;

    unsigned act_base = (unsigned)__cvta_generic_to_shared(s_act);
    unsigned wp_base  = act_base + 2176 * 4 + warp * 1024;  // 2 bufs x 512B per warp

    int wn = warp * 16;
    // warp-local weight staging: 16 rows x 32B (own 16 cols); 1 x 16B chunk per lane
    int wl_r = lane >> 1, wl_c = lane & 1;
    unsigned wdst_off = wl_r * 32 + wl_c * 16;
    int wsrc_off = wl_r * 128 + wn + wl_c * 8;

    // prefetch stage 0 (X=0, i0=0) into buf 0 (warp-local; before block sync is fine)
    CP_ASYNC16(wp_base + wdst_off, wq + wsrc_off);
    CP_COMMIT();

    // ldmatrix per-lane offsets
    int arow = (lane & 7) + (lane & 8);          // 0..15
    int acol = (lane & 16) ? 8 : 0;
    unsigned a_off0 = (arow * 136 + acol) * 2;               // act rows 0-15
    unsigned a_off1 = ((16 + arow) * 136 + acol) * 2;        // act rows 16-31
    unsigned wb_off = arow * 32 + acol * 2;                  // within warp slab

    int trow = lane >> 2, tcol = (lane & 3) * 2;

    __syncthreads();   // s_act visible to all warps

    // ---- QKV projection: warp-local double-buffered pipeline, no block barriers ----
    int buf = 0;
    for (int X = 0; X < 3; X++) {
        float acc[2][2][4] = {};   // [nt][mt][4]
        for (int kk = 0; kk < 8; kk++) {
            int s = X * 8 + kk;
            if (s < 23) {
                int s1 = s + 1;
                int X1 = s1 >> 3, i0 = (s1 & 7) * 16;
                const __half* w = (X1 == 0) ? wq : (X1 == 1) ? wk : wv;
                CP_ASYNC16(wp_base + (buf ^ 1) * 512 + wdst_off, w + i0 * 128 + wsrc_off);
                CP_COMMIT();
                CP_WAIT1();
            } else {
                CP_WAIT0();
            }
            __syncwarp();   // all lanes' cp.async copies visible within warp

            unsigned a0f[4], a1f[4], bf[4];
            ldsm_x4(a0f, act_base + a_off0 + kk * 32);
            ldsm_x4(a1f, act_base + a_off1 + kk * 32);
            ldsm_x4_t(bf, wp_base + buf * 512 + wb_off);
            mma16816(acc[0][0], a0f, bf[0], bf[1]);
            mma16816(acc[0][1], a1f, bf[0], bf[1]);
            mma16816(acc[1][0], a0f, bf[2], bf[3]);
            mma16816(acc[1][1], a1f, bf[2], bf[3]);

            buf ^= 1;   // ldmatrix.sync ordered all reads of buf before next prefetch
        }
        // store lrelu(result) as fp16 to own 16 columns of s_qh/s_kh/s_vh
        __half* dst = (X == 0) ? s_qh : (X == 1) ? s_kh : s_vh;
        #pragma unroll
        for (int nt = 0; nt < 2; nt++) {
            int colb = wn + nt * 8 + tcol;
            float* c0p = acc[nt][0];
            *(__half2*)&dst[trow * 136 + colb] = __floats2half2_rn(lrelu(c0p[0]), lrelu(c0p[1]));
            *(__half2*)&dst[(trow + 8) * 136 + colb] = __floats2half2_rn(lrelu(c0p[2]), lrelu(c0p[3]));
            float* c1p = acc[nt][1];
            *(__half2*)&dst[(16 + trow) * 136 + colb] = __floats2half2_rn(lrelu(c1p[0]), lrelu(c1p[1]));
        }
    }

    // All warps done with s_act + weight slabs before s_val overlays them.
    __syncthreads();

    // ================= warp-local attention: head h = warp ======================
    {
        int h = warp;
        {
            int r = 24 + (lane >> 2);
            int cu = (lane & 3) * 2;
            unsigned* vz = (unsigned*)s_vh;
            vz[r * 68 + h * 8 + cu]     = 0u;
            vz[r * 68 + h * 8 + cu + 1] = 0u;
        }
        __syncwarp();

        unsigned qh_base = act_base + 4224 * 4;
        unsigned kh_base = act_base + 6400 * 4;
        unsigned vh_base = act_base + 8576 * 4;
        unsigned hcol_off = (arow * 136 + h * 16 + acol) * 2;

        unsigned kq0[4], kq1[4], kb0[4], kb1[4];
        ldsm_x4(kq0, qh_base + hcol_off);
        ldsm_x4(kq1, qh_base + hcol_off + 16 * 272);
        ldsm_x4(kb0, kh_base + hcol_off);
        ldsm_x4(kb1, kh_base + hcol_off + 16 * 272);

        float sc[2][3][4] = {};
        mma16816(sc[0][0], kq0, kb0[0], kb0[2]);
        mma16816(sc[0][1], kq0, kb0[1], kb0[3]);
        mma16816(sc[0][2], kq0, kb1[0], kb1[2]);
        mma16816(sc[1][0], kq1, kb0[0], kb0[2]);
        mma16816(sc[1][1], kq1, kb0[1], kb0[3]);
        mma16816(sc[1][2], kq1, kb1[0], kb1[2]);

        int p2 = lane & 3, ql = lane >> 2;
        unsigned ah[3][3];
        #pragma unroll
        for (int g = 0; g < 3; g++) {
            int t = ql + 8 * g;
            float x[6];
            #pragma unroll
            for (int nt = 0; nt < 3; nt++) {
                #pragma unroll
                for (int p = 0; p < 2; p++) {
                    float raw = (g == 0) ? sc[0][nt][p]
                              : (g == 1) ? sc[0][nt][2 + p]
                                         : sc[1][nt][p];
                    int scol = nt * 8 + 2 * p2 + p;
                    x[nt * 2 + p] = (scol <= t) ? 0.25f * raw : -1e30f;
                }
            }
            float mx = x[0];
            #pragma unroll
            for (int j = 1; j < 6; j++) mx = fmaxf(mx, x[j]);
            mx = fmaxf(mx, __shfl_xor_sync(0xFFFFFFFF, mx, 1));
            mx = fmaxf(mx, __shfl_xor_sync(0xFFFFFFFF, mx, 2));
            float e[6], sum = 0.f;
            #pragma unroll
            for (int j = 0; j < 6; j++) { e[j] = __expf(x[j] - mx); sum += e[j]; }
            sum += __shfl_xor_sync(0xFFFFFFFF, sum, 1);
            sum += __shfl_xor_sync(0xFFFFFFFF, sum, 2);
            float inv = 1.f / sum;
            #pragma unroll
            for (int nt = 0; nt < 3; nt++)
                ah[g][nt] = packh2(e[nt * 2] * inv, e[nt * 2 + 1] * inv);
        }

        unsigned vb0[4], vb1[4];
        ldsm_x4_t(vb0, vh_base + hcol_off);
        ldsm_x4_t(vb1, vh_base + hcol_off + 16 * 272);

        unsigned A00[4] = { ah[0][0], ah[1][0], ah[0][1], ah[1][1] };
        unsigned A01[4] = { ah[2][0], 0u,       ah[2][1], 0u       };
        unsigned A10[4] = { ah[0][2], ah[1][2], 0u,       0u       };
        unsigned A11[4] = { ah[2][2], 0u,       0u,       0u       };

        float val[2][2][4] = {};
        #pragma unroll
        for (int ne = 0; ne < 2; ne++) {
            mma16816(val[0][ne], A00, vb0[2 * ne], vb0[2 * ne + 1]);
            mma16816(val[0][ne], A10, vb1[2 * ne], vb1[2 * ne + 1]);
            mma16816(val[1][ne], A01, vb0[2 * ne], vb0[2 * ne + 1]);
            mma16816(val[1][ne], A11, vb1[2 * ne], vb1[2 * ne + 1]);
        }

        #pragma unroll
        for (int ne = 0; ne < 2; ne++) {
            int colf = h * 16 + ne * 8 + 2 * p2;
            *(float2*)&s_val[ql * PAD + colf]        = make_float2(val[0][ne][0], val[0][ne][1]);
            *(float2*)&s_val[(ql + 8) * PAD + colf]  = make_float2(val[0][ne][2], val[0][ne][3]);
            *(float2*)&s_val[(16 + ql) * PAD + colf] = make_float2(val[1][ne][0], val[1][ne][1]);
        }
    }
    __syncthreads();

    // ---- load gcn under out-proj compute ----
    for (int idx = tid; idx < 1536; idx += 256) s_gcn[idx] = g_gcn[base + idx];

    // ---- value = lrelu(val @ out_w + out_b) ----
    int e0 = (tid & 15) * 4;
    int tg2 = tid >> 4;
    int t0 = tg2, t1 = tg2 + 16;
    int t1c = (t1 < Tc) ? t1 : 0;
    {
        float a0[4] = {}, a1[4] = {};
        #pragma unroll 2
        for (int i = 0; i < 128; i += 4) {
            float4 x0 = *(const float4*)&s_val[t0 * PAD + i];
            float4 x1 = *(const float4*)&s_val[t1c * PAD + i];
            #pragma unroll
            for (int u = 0; u < 4; u++) {
                float4 w4 = *(const float4*)&out_w[(i + u) * 64 + e0];
                float xu0 = (&x0.x)[u], xu1 = (&x1.x)[u];
                a0[0] += xu0 * w4.x; a0[1] += xu0 * w4.y; a0[2] += xu0 * w4.z; a0[3] += xu0 * w4.w;
                a1[0] += xu1 * w4.x; a1[1] += xu1 * w4.y; a1[2] += xu1 * w4.z; a1[3] += xu1 * w4.w;
            }
        }
        float4 ob = *(const float4*)&out_b[e0];
        float4 v0;
        v0.x = lrelu(a0[0] + ob.x); v0.y = lrelu(a0[1] + ob.y);
        v0.z = lrelu(a0[2] + ob.z); v0.w = lrelu(a0[3] + ob.w);
        *(float4*)&s_value[t0 * 64 + e0] = v0;
        if (t1 < Tc) {
            float4 v1;
            v1.x = lrelu(a1[0] + ob.x); v1.y = lrelu(a1[1] + ob.y);
            v1.z = lrelu(a1[2] + ob.z); v1.w = lrelu(a1[3] + ob.w);
            *(float4*)&s_value[t1 * 64 + e0] = v1;
        }
    }
    __syncthreads();

    // ---- gate + blend + residual ----
    {
        float g0[4] = {}, g1[4] = {};
        #pragma unroll 2
        for (int i = 0; i < 64; i += 4) {
            float4 x0 = *(const float4*)&s_gcn[t0 * 64 + i];
            float4 x1 = *(const float4*)&s_gcn[t1c * 64 + i];
            #pragma unroll
            for (int u = 0; u < 4; u++) {
                float4 w4 = *(const float4*)&gate_w[(i + u) * 64 + e0];
                float xu0 = (&x0.x)[u], xu1 = (&x1.x)[u];
                g0[0] += xu0 * w4.x; g0[1] += xu0 * w4.y; g0[2] += xu0 * w4.z; g0[3] += xu0 * w4.w;
                g1[0] += xu1 * w4.x; g1[1] += xu1 * w4.y; g1[2] += xu1 * w4.z; g1[3] += xu1 * w4.w;
            }
        }
        #pragma unroll 2
        for (int i = 0; i < 64; i += 4) {
            float4 x0 = *(const float4*)&s_value[t0 * 64 + i];
            float4 x1 = *(const float4*)&s_value[t1c * 64 + i];
            #pragma unroll
            for (int u = 0; u < 4; u++) {
                float4 w4 = *(const float4*)&gate_w[(64 + i + u) * 64 + e0];
                float xu0 = (&x0.x)[u], xu1 = (&x1.x)[u];
                g0[0] += xu0 * w4.x; g0[1] += xu0 * w4.y; g0[2] += xu0 * w4.z; g0[3] += xu0 * w4.w;
                g1[0] += xu1 * w4.x; g1[1] += xu1 * w4.y; g1[2] += xu1 * w4.z; g1[3] += xu1 * w4.w;
            }
        }
        float4 gb = *(const float4*)&gate_b[e0];
        {
            float4 hd = *(const float4*)&hidden[base + t0 * 64 + e0];
            float zx = 1.f / (1.f + expf(-(g0[0] + gb.x)));
            float zy = 1.f / (1.f + expf(-(g0[1] + gb.y)));
            float zz = 1.f / (1.f + expf(-(g0[2] + gb.z)));
            float zw = 1.f / (1.f + expf(-(g0[3] + gb.w)));
            const float* gc = &s_gcn[t0 * 64 + e0];
            const float* vv = &s_value[t0 * 64 + e0];
            float4 o;
            o.x = zx * gc[0] + (1.f - zx) * vv[0] + hd.x;
            o.y = zy * gc[1] + (1.f - zy) * vv[1] + hd.y;
            o.z = zz * gc[2] + (1.f - zz) * vv[2] + hd.z;
            o.w = zw * gc[3] + (1.f - zw) * vv[3] + hd.w;
            *(float4*)&out[base + t0 * 64 + e0] = o;
        }
        if (t1 < Tc) {
            float4 hd = *(const float4*)&hidden[base + t1 * 64 + e0];
            float zx = 1.f / (1.f + expf(-(g1[0] + gb.x)));
            float zy = 1.f / (1.f + expf(-(g1[1] + gb.y)));
            float zz = 1.f / (1.f + expf(-(g1[2] + gb.z)));
            float zw = 1.f / (1.f + expf(-(g1[3] + gb.w)));
            const float* gc = &s_gcn[t1 * 64 + e0];
            const float* vv = &s_value[t1 * 64 + e0];
            float4 o;
            o.x = zx * gc[0] + (1.f - zx) * vv[0] + hd.x;
            o.y = zy * gc[1] + (1.f - zy) * vv[1] + hd.y;
            o.z = zz * gc[2] + (1.f - zz) * vv[2] + hd.z;
            o.w = zw * gc[3] + (1.f - zw) * vv[3] + hd.w;
            *(float4*)&out[base + t1 * 64 + e0] = o;
        }
    }
}

// ---------------- launch ----------------
extern "C" void kernel_launch(void* const* d_in, const int* in_sizes, int n_in,
                              void* d_out, int out_size) {
    const float* hidden   = (const float*)d_in[0];
    const float* tXin     = (const float*)d_in[1];
    const float* matrix   = (const float*)d_in[2];
    const float* gcn_w    = (const float*)d_in[3];
    const float* gcn_b    = (const float*)d_in[4];
    const float* node_emb = (const float*)d_in[5];
    const float* tproj_w  = (const float*)d_in[6];
    const float* tproj_b  = (const float*)d_in[7];
    const float* WK       = (const float*)d_in[8];
    const float* WQ       = (const float*)d_in[9];
    const float* WV       = (const float*)d_in[10];
    const float* out_w    = (const float*)d_in[11];
    const float* out_b    = (const float*)d_in[12];
    const float* gate_w   = (const float*)d_in[13];
    const float* gate_b   = (const float*)d_in[14];
    float* out = (float*)d_out;

    cudaFuncSetAttribute(k_attn, cudaFuncAttributeMaxDynamicSharedMemorySize, ATTN_SMEM_BYTES);

    k_tfeat<<<Bc, 64>>>(tXin, tproj_w, tproj_b);
    k_gcn<<<dim3(6, Tc, Bc), 256>>>(matrix, hidden, gcn_w, gcn_b);
    k_weff<<<dim3(16, 82, 3), 256>>>(WQ, WK, WV, node_emb);
    k_attn<<<BNc, 256, ATTN_SMEM_BYTES>>>(hidden, tXin, out_w, out_b, gate_w, gate_b, out);
}

// round 14
// speedup vs baseline: 1.8394x; 1.2379x over previous
#include <cuda_runtime.h>
#include <cuda_fp16.h>
#include <math.h>

#define Bc   8
#define Nc   325
#define Tc   24
#define Dc   64
#define Hc   8
#define Mc   16
#define E2c  128
#define BNc  2600   // Bc*Nc

// ---------------- device scratch ----------------
__device__ float g_tfeat[Bc * Mc];                            // (B,16)
__device__ float g_gcn[(size_t)Bc * Nc * Tc * Dc];            // (B,N,T,D) ~16MB
__device__ __align__(16) __half g_weff[(size_t)3 * BNc * E2c * E2c]; // fp16 ~256MB
__device__ __align__(16) __half g_outw_h[E2c * Dc];           // fp16 out_w 128x64
__device__ __align__(16) __half g_gatew_h[E2c * Dc];          // fp16 gate_w 128x64

__device__ __forceinline__ float lrelu(float x) { return x > 0.f ? x : 0.1f * x; }

#define CP_ASYNC16(sdst, gsrc) \
    asm volatile("cp.async.cg.shared.global [%0], [%1], 16;" :: "r"(sdst), "l"(gsrc) : "memory")
#define CP_COMMIT() asm volatile("cp.async.commit_group;" ::: "memory")
#define CP_WAIT1()  asm volatile("cp.async.wait_group 1;" ::: "memory")
#define CP_WAIT0()  asm volatile("cp.async.wait_group 0;" ::: "memory")

__device__ __forceinline__ void ldsm_x4(unsigned* r, unsigned addr) {
    asm volatile("ldmatrix.sync.aligned.m8n8.x4.shared.b16 {%0,%1,%2,%3}, [%4];"
                 : "=r"(r[0]), "=r"(r[1]), "=r"(r[2]), "=r"(r[3]) : "r"(addr));
}
__device__ __forceinline__ void ldsm_x4_t(unsigned* r, unsigned addr) {
    asm volatile("ldmatrix.sync.aligned.m8n8.x4.trans.shared.b16 {%0,%1,%2,%3}, [%4];"
                 : "=r"(r[0]), "=r"(r[1]), "=r"(r[2]), "=r"(r[3]) : "r"(addr));
}
__device__ __forceinline__ void mma16816(float* c, const unsigned* a, unsigned b0, unsigned b1) {
    asm volatile("mma.sync.aligned.m16n8k16.row.col.f32.f16.f16.f32 "
                 "{%0,%1,%2,%3}, {%4,%5,%6,%7}, {%8,%9}, {%0,%1,%2,%3};"
                 : "+f"(c[0]), "+f"(c[1]), "+f"(c[2]), "+f"(c[3])
                 : "r"(a[0]), "r"(a[1]), "r"(a[2]), "r"(a[3]), "r"(b0), "r"(b1));
}
__device__ __forceinline__ unsigned packh2(float a, float b) {
    __half2 h = __floats2half2_rn(a, b);
    return *reinterpret_cast<unsigned*>(&h);
}

// ---------------- Kernel 0: fp16 weight prep ----------------
__global__ void k_prep(const float* __restrict__ ow, const float* __restrict__ gw) {
    int i = blockIdx.x * 256 + threadIdx.x;   // grid 32 x 256 = 8192
    g_outw_h[i]  = __float2half(ow[i]);
    g_gatew_h[i] = __float2half(gw[i]);
}

// ---------------- Kernel 1: tfeat ----------------
__global__ void k_tfeat(const float* __restrict__ tXin,
                        const float* __restrict__ tpw,
                        const float* __restrict__ tpb) {
    __shared__ float s_mean[Dc];
    int b = blockIdx.x;
    int d = threadIdx.x;  // 64 threads
    const float* p = tXin + (size_t)b * Nc * Tc * Dc;  // n = 0 slice
    float s = 0.f;
    #pragma unroll
    for (int t = 0; t < Tc; t++) s += p[t * Dc + d];
    s_mean[d] = s * (1.0f / Tc);
    __syncthreads();
    if (d < Mc) {
        float acc = tpb[d];
        #pragma unroll
        for (int i = 0; i < Dc; i++) acc += s_mean[i] * tpw[i * Mc + d];
        g_tfeat[b * Mc + d] = tanhf(acc);
    }
}

// ---------------- Kernel 2: support GEMM + GCN, tensor cores --------------------
__global__ __launch_bounds__(256) void k_gcn(const float* __restrict__ matrix,
                                             const float* __restrict__ hidden,
                                             const float* __restrict__ gcn_w,
                                             const float* __restrict__ gcn_b) {
    __shared__ __half sA[64][40];
    __shared__ __half sB[32][72];
    __shared__ __half sS[64][72];
    __shared__ __half sW[64][72];
    int tid = threadIdx.x, lane = tid & 31, warp = tid >> 5;
    int nt = blockIdx.x, t = blockIdx.y, b = blockIdx.z;
    int n0 = nt * 64;

    for (int idx = tid; idx < 4096; idx += 256)
        sW[idx >> 6][idx & 63] = __float2half(gcn_w[idx]);

    const float* Mrow = matrix + ((size_t)(b * Tc + t) * Nc) * Nc;

    unsigned sA_b = (unsigned)__cvta_generic_to_shared(&sA[0][0]);
    unsigned sB_b = (unsigned)__cvta_generic_to_shared(&sB[0][0]);
    unsigned sS_b = (unsigned)__cvta_generic_to_shared(&sS[0][0]);
    unsigned sW_b = (unsigned)__cvta_generic_to_shared(&sW[0][0]);

    int r0 = (warp >> 1) * 16;
    int c0 = (warp & 1) * 32;
    int arow = (lane & 7) + (lane & 8);
    int acol8 = (lane & 16) ? 8 : 0;
    int trow = lane >> 2, p2 = lane & 3;

    float acc[4][4] = {};
    for (int kc = 0; kc < 11; kc++) {
        int m0 = kc * 32;
        __syncthreads();
        for (int idx = tid; idx < 2048; idx += 256) {
            int i = idx >> 5, j = idx & 31;
            int n = n0 + i, m = m0 + j;
            float v = (n < Nc && m < Nc) ? Mrow[(size_t)n * Nc + m] : 0.f;
            sA[i][j] = __float2half(v);
        }
        for (int idx = tid; idx < 2048; idx += 256) {
            int j = idx >> 6, d = idx & 63;
            int m = m0 + j;
            float v = (m < Nc) ? hidden[((size_t)(b * Nc + m) * Tc + t) * Dc + d] : 0.f;
            sB[j][d] = __float2half(v);
        }
        __syncthreads();
        #pragma unroll
        for (int ks = 0; ks < 2; ks++) {
            unsigned af[4], bf0[4], bf1[4];
            ldsm_x4(af,    sA_b + ((r0 + arow) * 40 + ks * 16 + acol8) * 2);
            ldsm_x4_t(bf0, sB_b + ((ks * 16 + arow) * 72 + c0 + acol8) * 2);
            ldsm_x4_t(bf1, sB_b + ((ks * 16 + arow) * 72 + c0 + 16 + acol8) * 2);
            mma16816(acc[0], af, bf0[0], bf0[1]);
            mma16816(acc[1], af, bf0[2], bf0[3]);
            mma16816(acc[2], af, bf1[0], bf1[1]);
            mma16816(acc[3], af, bf1[2], bf1[3]);
        }
    }

    #pragma unroll
    for (int ntile = 0; ntile < 4; ntile++) {
        int col = c0 + ntile * 8 + 2 * p2;
        *(__half2*)&sS[r0 + trow][col]     = __floats2half2_rn(acc[ntile][0], acc[ntile][1]);
        *(__half2*)&sS[r0 + trow + 8][col] = __floats2half2_rn(acc[ntile][2], acc[ntile][3]);
    }
    __syncthreads();

    float acc2[4][4] = {};
    #pragma unroll
    for (int ks = 0; ks < 4; ks++) {
        unsigned af[4], bf0[4], bf1[4];
        ldsm_x4(af,    sS_b + ((r0 + arow) * 72 + ks * 16 + acol8) * 2);
        ldsm_x4_t(bf0, sW_b + ((ks * 16 + arow) * 72 + c0 + acol8) * 2);
        ldsm_x4_t(bf1, sW_b + ((ks * 16 + arow) * 72 + c0 + 16 + acol8) * 2);
        mma16816(acc2[0], af, bf0[0], bf0[1]);
        mma16816(acc2[1], af, bf0[2], bf0[3]);
        mma16816(acc2[2], af, bf1[0], bf1[1]);
        mma16816(acc2[3], af, bf1[2], bf1[3]);
    }

    #pragma unroll
    for (int ntile = 0; ntile < 4; ntile++) {
        int col = c0 + ntile * 8 + 2 * p2;
        float bx = gcn_b[col], by = gcn_b[col + 1];
        int n1 = n0 + r0 + trow, n2 = n1 + 8;
        if (n1 < Nc) {
            float2 o = make_float2(fmaxf(acc2[ntile][0] + bx, 0.f),
                                   fmaxf(acc2[ntile][1] + by, 0.f));
            *(float2*)&g_gcn[((size_t)(b * Nc + n1) * Tc + t) * Dc + col] = o;
        }
        if (n2 < Nc) {
            float2 o = make_float2(fmaxf(acc2[ntile][2] + bx, 0.f),
                                   fmaxf(acc2[ntile][3] + by, 0.f));
            *(float2*)&g_gcn[((size_t)(b * Nc + n2) * Tc + t) * Dc + col] = o;
        }
    }
}

// ---------------- Kernel 3: Weff build (fp16 out), W in regs, 32 rows/block -----
__global__ __launch_bounds__(256) void k_weff(const float* __restrict__ WQ,
                                              const float* __restrict__ WK,
                                              const float* __restrict__ WV,
                                              const float* __restrict__ node_emb) {
    __shared__ float s_emb[32][16];
    int tid = threadIdx.x;
    int cx = blockIdx.x;
    int by = blockIdx.y;
    int X  = blockIdx.z;
    const float* W = (X == 0) ? WQ : (X == 1) ? WK : WV;
    int c0 = cx * 1024 + tid * 4;

    float4 w[16];
    #pragma unroll
    for (int m = 0; m < 16; m++) w[m] = *(const float4*)&W[(size_t)m * 16384 + c0];

    for (int idx = tid; idx < 512; idx += 256) {
        int row = idx >> 4, m = idx & 15;
        int bn = by * 32 + row;
        if (bn < BNc) {
            int b = bn / Nc, n = bn - b * Nc;
            s_emb[row][m] = node_emb[n * Mc + m] * g_tfeat[b * Mc + m];
        }
    }
    __syncthreads();

    #pragma unroll 4
    for (int row = 0; row < 32; row++) {
        int bn = by * 32 + row;
        if (bn >= BNc) break;
        float4 acc = make_float4(0.f, 0.f, 0.f, 0.f);
        #pragma unroll
        for (int m = 0; m < 16; m++) {
            float e = s_emb[row][m];
            acc.x += e * w[m].x; acc.y += e * w[m].y;
            acc.z += e * w[m].z; acc.w += e * w[m].w;
        }
        __half2 h0 = __floats2half2_rn(acc.x, acc.y);
        __half2 h1 = __floats2half2_rn(acc.z, acc.w);
        __half2* dst = (__half2*)&g_weff[((size_t)X * BNc + bn) * 16384 + c0];
        dst[0] = h0; dst[1] = h1;
    }
}

// ---------------- Kernel 4: fused per-(b,n) attention path ----------------------
// smem (float units), total 10752 floats = 43008B (4 CTAs/SM):
//   [0, 2176)      s_act fp16 32x136 (proj)   | s_valh fp16 32x136 overlay (epilogue)
//   [2176, 4224)   proj per-warp weight slabs | s_wb epilogue weight stage 2x1152 halfs
//   [4224, 6400)   s_qh fp16 32x136           | s_gateh fp16 32x136 [gcn|value] overlay
//   [6400, 8576)   s_kh fp16 32x136
//   [8576, 10752)  s_vh fp16 32x136
#define ATTN_SMEM_FLOATS 10752
#define ATTN_SMEM_BYTES  (ATTN_SMEM_FLOATS * 4)

__global__ __launch_bounds__(256, 4) void k_attn(const float* __restrict__ hidden,
                                                 const float* __restrict__ tXin,
                                                 const float* __restrict__ out_b,
                                                 const float* __restrict__ gate_b,
                                                 float* __restrict__ out) {
    extern __shared__ float sm[];
    __half* s_act   = (__half*)sm;              // 32x136 halfs
    __half* s_qh    = (__half*)(sm + 4224);
    __half* s_kh    = (__half*)(sm + 6400);
    __half* s_vh    = (__half*)(sm + 8576);
    __half* s_valh  = s_act;                    // overlay (epilogue)
    __half* s_gateh = s_qh;                     // overlay (epilogue) [gcn | value]

    int tid  = threadIdx.x;
    int lane = tid & 31;
    int warp = tid >> 5;
    int bn   = blockIdx.x;
    size_t base = (size_t)bn * (Tc * Dc);

    // ---- stage activations as fp16 (rows 24-31 zero) ----
    for (int idx = tid; idx < 4096; idx += 256) {
        int t = idx >> 7, i = idx & 127;
        float vv = 0.f;
        if (t < Tc) vv = (i < 64) ? hidden[base + t * 64 + i] : tXin[base + t * 64 + (i - 64)];
        s_act[t * 136 + i] = __float2half(vv);
    }

    const __half* wq = g_weff + (size_t)bn * 16384;
    const __half* wk = g_weff + ((size_t)BNc + bn) * 16384;
    const __half* wv = g_weff + ((size_t)2 * BNc + bn) * 16384;

    unsigned act_base = (unsigned)__cvta_generic_to_shared(s_act);
    unsigned wp_base  = act_base + 2176 * 4 + warp * 1024;  // 2 bufs x 512B per warp
    unsigned swb      = act_base + 2176 * 4;                // epilogue stage base

    int wn = warp * 16;
    int wl_r = lane >> 1, wl_c = lane & 1;
    unsigned wdst_off = wl_r * 32 + wl_c * 16;
    int wsrc_off = wl_r * 128 + wn + wl_c * 8;

    CP_ASYNC16(wp_base + wdst_off, wq + wsrc_off);
    CP_COMMIT();

    int arow = (lane & 7) + (lane & 8);          // 0..15
    int acol = (lane & 16) ? 8 : 0;
    unsigned a_off0 = (arow * 136 + acol) * 2;
    unsigned a_off1 = ((16 + arow) * 136 + acol) * 2;
    unsigned wb_off = arow * 32 + acol * 2;

    int trow = lane >> 2, tcol = (lane & 3) * 2;
    int p2 = lane & 3, ql = lane >> 2;

    __syncthreads();   // s_act visible

    // ---- QKV projection: warp-local double-buffered pipeline ----
    int buf = 0;
    for (int X = 0; X < 3; X++) {
        float acc[2][2][4] = {};
        for (int kk = 0; kk < 8; kk++) {
            int s = X * 8 + kk;
            if (s < 23) {
                int s1 = s + 1;
                int X1 = s1 >> 3, i0 = (s1 & 7) * 16;
                const __half* w = (X1 == 0) ? wq : (X1 == 1) ? wk : wv;
                CP_ASYNC16(wp_base + (buf ^ 1) * 512 + wdst_off, w + i0 * 128 + wsrc_off);
                CP_COMMIT();
                CP_WAIT1();
            } else {
                CP_WAIT0();
            }
            __syncwarp();

            unsigned a0f[4], a1f[4], bf[4];
            ldsm_x4(a0f, act_base + a_off0 + kk * 32);
            ldsm_x4(a1f, act_base + a_off1 + kk * 32);
            ldsm_x4_t(bf, wp_base + buf * 512 + wb_off);
            mma16816(acc[0][0], a0f, bf[0], bf[1]);
            mma16816(acc[0][1], a1f, bf[0], bf[1]);
            mma16816(acc[1][0], a0f, bf[2], bf[3]);
            mma16816(acc[1][1], a1f, bf[2], bf[3]);

            buf ^= 1;
        }
        __half* dst = (X == 0) ? s_qh : (X == 1) ? s_kh : s_vh;
        #pragma unroll
        for (int nt = 0; nt < 2; nt++) {
            int colb = wn + nt * 8 + tcol;
            float* c0p = acc[nt][0];
            *(__half2*)&dst[trow * 136 + colb] = __floats2half2_rn(lrelu(c0p[0]), lrelu(c0p[1]));
            *(__half2*)&dst[(trow + 8) * 136 + colb] = __floats2half2_rn(lrelu(c0p[2]), lrelu(c0p[3]));
            float* c1p = acc[nt][1];
            *(__half2*)&dst[(16 + trow) * 136 + colb] = __floats2half2_rn(lrelu(c1p[0]), lrelu(c1p[1]));
        }
    }

    // all warps done with s_act + proj slabs before overlays are written
    __syncthreads();

    // ================= warp-local attention: head h = warp ======================
    float val[2][2][4] = {};
    {
        int h = warp;
        {
            int r = 24 + (lane >> 2);
            int cu = (lane & 3) * 2;
            unsigned* vz = (unsigned*)s_vh;
            vz[r * 68 + h * 8 + cu]     = 0u;
            vz[r * 68 + h * 8 + cu + 1] = 0u;
        }
        __syncwarp();

        unsigned qh_base = act_base + 4224 * 4;
        unsigned kh_base = act_base + 6400 * 4;
        unsigned vh_base = act_base + 8576 * 4;
        unsigned hcol_off = (arow * 136 + h * 16 + acol) * 2;

        unsigned kq0[4], kq1[4], kb0[4], kb1[4];
        ldsm_x4(kq0, qh_base + hcol_off);
        ldsm_x4(kq1, qh_base + hcol_off + 16 * 272);
        ldsm_x4(kb0, kh_base + hcol_off);
        ldsm_x4(kb1, kh_base + hcol_off + 16 * 272);

        float sc[2][3][4] = {};
        mma16816(sc[0][0], kq0, kb0[0], kb0[2]);
        mma16816(sc[0][1], kq0, kb0[1], kb0[3]);
        mma16816(sc[0][2], kq0, kb1[0], kb1[2]);
        mma16816(sc[1][0], kq1, kb0[0], kb0[2]);
        mma16816(sc[1][1], kq1, kb0[1], kb0[3]);
        mma16816(sc[1][2], kq1, kb1[0], kb1[2]);

        unsigned ah[3][3];
        #pragma unroll
        for (int g = 0; g < 3; g++) {
            int t = ql + 8 * g;
            float x[6];
            #pragma unroll
            for (int nt = 0; nt < 3; nt++) {
                #pragma unroll
                for (int p = 0; p < 2; p++) {
                    float raw = (g == 0) ? sc[0][nt][p]
                              : (g == 1) ? sc[0][nt][2 + p]
                                         : sc[1][nt][p];
                    int scol = nt * 8 + 2 * p2 + p;
                    x[nt * 2 + p] = (scol <= t) ? 0.25f * raw : -1e30f;
                }
            }
            float mx = x[0];
            #pragma unroll
            for (int j = 1; j < 6; j++) mx = fmaxf(mx, x[j]);
            mx = fmaxf(mx, __shfl_xor_sync(0xFFFFFFFF, mx, 1));
            mx = fmaxf(mx, __shfl_xor_sync(0xFFFFFFFF, mx, 2));
            float e[6], sum = 0.f;
            #pragma unroll
            for (int j = 0; j < 6; j++) { e[j] = __expf(x[j] - mx); sum += e[j]; }
            sum += __shfl_xor_sync(0xFFFFFFFF, sum, 1);
            sum += __shfl_xor_sync(0xFFFFFFFF, sum, 2);
            float inv = 1.f / sum;
            #pragma unroll
            for (int nt = 0; nt < 3; nt++)
                ah[g][nt] = packh2(e[nt * 2] * inv, e[nt * 2 + 1] * inv);
        }

        unsigned vb0[4], vb1[4];
        ldsm_x4_t(vb0, vh_base + hcol_off);
        ldsm_x4_t(vb1, vh_base + hcol_off + 16 * 272);

        unsigned A00[4] = { ah[0][0], ah[1][0], ah[0][1], ah[1][1] };
        unsigned A01[4] = { ah[2][0], 0u,       ah[2][1], 0u       };
        unsigned A10[4] = { ah[0][2], ah[1][2], 0u,       0u       };
        unsigned A11[4] = { ah[2][2], 0u,       0u,       0u       };

        #pragma unroll
        for (int ne = 0; ne < 2; ne++) {
            mma16816(val[0][ne], A00, vb0[2 * ne], vb0[2 * ne + 1]);
            mma16816(val[0][ne], A10, vb1[2 * ne], vb1[2 * ne + 1]);
            mma16816(val[1][ne], A01, vb0[2 * ne], vb0[2 * ne + 1]);
            mma16816(val[1][ne], A11, vb1[2 * ne], vb1[2 * ne + 1]);
        }

        // store val as fp16 into s_valh (own 16 cols); zero pad rows 24-31
        {
            int r = 24 + (lane >> 3);          // 4 rows per... lanes 8 per row: rows 24..27
            int cu = (lane & 7) * 2;
            // zero rows 24-31 of own 16 cols: 8 rows x 16 cols = 128 halfs; 32 lanes x 4 halfs
            int zr = 24 + (lane >> 2);         // rows 24..31
            int zc = (lane & 3) * 4;           // 4 halfs
            *(float2*)&s_valh[zr * 136 + h * 16 + zc] = make_float2(0.f, 0.f);
            (void)r; (void)cu;
        }
        #pragma unroll
        for (int ne = 0; ne < 2; ne++) {
            int colf = h * 16 + ne * 8 + 2 * p2;
            *(__half2*)&s_valh[ql * 136 + colf]        = __floats2half2_rn(val[0][ne][0], val[0][ne][1]);
            *(__half2*)&s_valh[(ql + 8) * 136 + colf]  = __floats2half2_rn(val[0][ne][2], val[0][ne][3]);
            *(__half2*)&s_valh[(16 + ql) * 136 + colf] = __floats2half2_rn(val[1][ne][0], val[1][ne][1]);
        }
    }

    // ---- stage gcn fp16 into s_gateh cols 0-63; zero rows 24-31 (all 128 cols) ----
    // (s_qh region: all warps past attention only after the barrier below; but we
    //  must not write s_gateh before all warps finished reading s_qh/s_kh -> sync first)
    __syncthreads();

    for (int idx = tid; idx < 1536; idx += 256) {
        int t = idx >> 6, d = idx & 63;
        s_gateh[t * 136 + d] = __float2half(g_gcn[base + idx]);
    }
    for (int idx = tid; idx < 1024; idx += 256) {
        int r = 24 + (idx >> 7), c = idx & 127;
        s_gateh[r * 136 + c] = __float2half(0.f);
    }

    // ================= epilogue on tensor cores =================================
    int mg = warp >> 2, ng = warp & 3;     // 2 m-tiles x 4 n-tiles (16 cols each)
    unsigned aV_off = ((mg * 16 + arow) * 136 + acol) * 2;
    unsigned bW_off = (arow * 72 + ng * 16 + acol) * 2;
    int st_r = tid >> 3, st_s = tid & 7;   // staging: threads<128: 16 rows x 8 segs
    unsigned st_dst = st_r * 144 + st_s * 16;
    int st_src = st_r * 64 + st_s * 8;

    // prefetch out_w chunk 0
    if (tid < 128) CP_ASYNC16(swb + st_dst, g_outw_h + st_src);
    CP_COMMIT();

    float vacc[2][4] = {};
    int ebuf = 0;
    for (int kk = 0; kk < 8; kk++) {
        if (kk < 7) {
            if (tid < 128) CP_ASYNC16(swb + (ebuf ^ 1) * 2304 + st_dst,
                                      g_outw_h + (kk + 1) * 1024 + st_src);
            CP_COMMIT();
            CP_WAIT1();
        } else {
            CP_WAIT0();
        }
        __syncthreads();
        unsigned aF[4], bF[4];
        ldsm_x4(aF, act_base + aV_off + kk * 32);
        ldsm_x4_t(bF, swb + ebuf * 2304 + bW_off);
        mma16816(vacc[0], aF, bF[0], bF[1]);
        mma16816(vacc[1], aF, bF[2], bF[3]);
        __syncthreads();
        ebuf ^= 1;
    }

    // value = lrelu(vacc + out_b); keep in regs; store fp16 into s_gateh cols 64+
    float vv_[2][4];
    #pragma unroll
    for (int nt = 0; nt < 2; nt++) {
        int col = ng * 16 + nt * 8 + 2 * p2;
        float bx = out_b[col], by = out_b[col + 1];
        vv_[nt][0] = lrelu(vacc[nt][0] + bx);
        vv_[nt][1] = lrelu(vacc[nt][1] + by);
        vv_[nt][2] = lrelu(vacc[nt][2] + bx);
        vv_[nt][3] = lrelu(vacc[nt][3] + by);
        int r0a = mg * 16 + trow;            // always < 24
        int r1a = r0a + 8;                   // valid only for mg==0
        *(__half2*)&s_gateh[r0a * 136 + 64 + col] = __floats2half2_rn(vv_[nt][0], vv_[nt][1]);
        if (mg == 0)
            *(__half2*)&s_gateh[r1a * 136 + 64 + col] = __floats2half2_rn(vv_[nt][2], vv_[nt][3]);
    }
    __syncthreads();

    // prefetch gate_w chunk 0
    if (tid < 128) CP_ASYNC16(swb + st_dst, g_gatew_h + st_src);
    CP_COMMIT();

    float gacc[2][4] = {};
    ebuf = 0;
    for (int kk = 0; kk < 8; kk++) {
        if (kk < 7) {
            if (tid < 128) CP_ASYNC16(swb + (ebuf ^ 1) * 2304 + st_dst,
                                      g_gatew_h + (kk + 1) * 1024 + st_src);
            CP_COMMIT();
            CP_WAIT1();
        } else {
            CP_WAIT0();
        }
        __syncthreads();
        unsigned aF[4], bF[4];
        ldsm_x4(aF, act_base + 4224 * 4 + aV_off + kk * 32);   // s_gateh
        ldsm_x4_t(bF, swb + ebuf * 2304 + bW_off);
        mma16816(gacc[0], aF, bF[0], bF[1]);
        mma16816(gacc[1], aF, bF[2], bF[3]);
        __syncthreads();
        ebuf ^= 1;
    }

    // ---- blend + residual, straight from fragments ----
    #pragma unroll
    for (int nt = 0; nt < 2; nt++) {
        int col = ng * 16 + nt * 8 + 2 * p2;
        float bgx = gate_b[col], bgy = gate_b[col + 1];
        int r0a = mg * 16 + trow;
        {
            float zx = 1.f / (1.f + __expf(-(gacc[nt][0] + bgx)));
            float zy = 1.f / (1.f + __expf(-(gacc[nt][1] + bgy)));
            float2 gc = __half22float2(*(__half2*)&s_gateh[r0a * 136 + col]);
            float2 hd = *(const float2*)&hidden[base + r0a * 64 + col];
            float2 o;
            o.x = zx * gc.x + (1.f - zx) * vv_[nt][0] + hd.x;
            o.y = zy * gc.y + (1.f - zy) * vv_[nt][1] + hd.y;
            *(float2*)&out[base + r0a * 64 + col] = o;
        }
        if (mg == 0) {
            int r1a = r0a + 8;
            float zx = 1.f / (1.f + __expf(-(gacc[nt][2] + bgx)));
            float zy = 1.f / (1.f + __expf(-(gacc[nt][3] + bgy)));
            float2 gc = __half22float2(*(__half2*)&s_gateh[r1a * 136 + col]);
            float2 hd = *(const float2*)&hidden[base + r1a * 64 + col];
            float2 o;
            o.x = zx * gc.x + (1.f - zx) * vv_[nt][2] + hd.x;
            o.y = zy * gc.y + (1.f - zy) * vv_[nt][3] + hd.y;
            *(float2*)&out[base + r1a * 64 + col] = o;
        }
    }
}

// ---------------- launch ----------------
extern "C" void kernel_launch(void* const* d_in, const int* in_sizes, int n_in,
                              void* d_out, int out_size) {
    const float* hidden   = (const float*)d_in[0];
    const float* tXin     = (const float*)d_in[1];
    const float* matrix   = (const float*)d_in[2];
    const float* gcn_w    = (const float*)d_in[3];
    const float* gcn_b    = (const float*)d_in[4];
    const float* node_emb = (const float*)d_in[5];
    const float* tproj_w  = (const float*)d_in[6];
    const float* tproj_b  = (const float*)d_in[7];
    const float* WK       = (const float*)d_in[8];
    const float* WQ       = (const float*)d_in[9];
    const float* WV       = (const float*)d_in[10];
    const float* out_w    = (const float*)d_in[11];
    const float* out_b    = (const float*)d_in[12];
    const float* gate_w   = (const float*)d_in[13];
    const float* gate_b   = (const float*)d_in[14];
    float* out = (float*)d_out;

    cudaFuncSetAttribute(k_attn, cudaFuncAttributeMaxDynamicSharedMemorySize, ATTN_SMEM_BYTES);

    k_tfeat<<<Bc, 64>>>(tXin, tproj_w, tproj_b);
    k_prep<<<32, 256>>>(out_w, gate_w);
    k_gcn<<<dim3(6, Tc, Bc), 256>>>(matrix, hidden, gcn_w, gcn_b);
    k_weff<<<dim3(16, 82, 3), 256>>>(WQ, WK, WV, node_emb);
    k_attn<<<BNc, 256, ATTN_SMEM_BYTES>>>(hidden, tXin, out_b, gate_b, out);
}

// round 15
// speedup vs baseline: 1.8489x; 1.0052x over previous
#include <cuda_runtime.h>
#include <cuda_fp16.h>
#include <math.h>

#define Bc   8
#define Nc   325
#define Tc   24
#define Dc   64
#define Hc   8
#define Mc   16
#define E2c  128
#define BNc  2600   // Bc*Nc

// ---------------- device scratch ----------------
__device__ float g_tfeat[Bc * Mc];                            // (B,16)
__device__ float g_gcn[(size_t)Bc * Nc * Tc * Dc];            // (B,N,T,D) ~16MB
__device__ __align__(16) __half g_weff[(size_t)3 * BNc * E2c * E2c]; // fp16 ~256MB
__device__ __align__(16) __half g_outw_h[E2c * Dc];           // fp16 out_w 128x64
__device__ __align__(16) __half g_gatew_h[E2c * Dc];          // fp16 gate_w 128x64

__device__ __forceinline__ float lrelu(float x) { return x > 0.f ? x : 0.1f * x; }

#define CP_ASYNC16(sdst, gsrc) \
    asm volatile("cp.async.cg.shared.global [%0], [%1], 16;" :: "r"(sdst), "l"(gsrc) : "memory")
#define CP_COMMIT() asm volatile("cp.async.commit_group;" ::: "memory")
#define CP_WAIT1()  asm volatile("cp.async.wait_group 1;" ::: "memory")
#define CP_WAIT0()  asm volatile("cp.async.wait_group 0;" ::: "memory")

__device__ __forceinline__ void ldsm_x4(unsigned* r, unsigned addr) {
    asm volatile("ldmatrix.sync.aligned.m8n8.x4.shared.b16 {%0,%1,%2,%3}, [%4];"
                 : "=r"(r[0]), "=r"(r[1]), "=r"(r[2]), "=r"(r[3]) : "r"(addr));
}
__device__ __forceinline__ void ldsm_x4_t(unsigned* r, unsigned addr) {
    asm volatile("ldmatrix.sync.aligned.m8n8.x4.trans.shared.b16 {%0,%1,%2,%3}, [%4];"
                 : "=r"(r[0]), "=r"(r[1]), "=r"(r[2]), "=r"(r[3]) : "r"(addr));
}
__device__ __forceinline__ void mma16816(float* c, const unsigned* a, unsigned b0, unsigned b1) {
    asm volatile("mma.sync.aligned.m16n8k16.row.col.f32.f16.f16.f32 "
                 "{%0,%1,%2,%3}, {%4,%5,%6,%7}, {%8,%9}, {%0,%1,%2,%3};"
                 : "+f"(c[0]), "+f"(c[1]), "+f"(c[2]), "+f"(c[3])
                 : "r"(a[0]), "r"(a[1]), "r"(a[2]), "r"(a[3]), "r"(b0), "r"(b1));
}
__device__ __forceinline__ unsigned packh2(float a, float b) {
    __half2 h = __floats2half2_rn(a, b);
    return *reinterpret_cast<unsigned*>(&h);
}

// ---------------- Kernel 0: fp16 weight prep ----------------
__global__ void k_prep(const float* __restrict__ ow, const float* __restrict__ gw) {
    int i = blockIdx.x * 256 + threadIdx.x;   // grid 32 x 256 = 8192
    g_outw_h[i]  = __float2half(ow[i]);
    g_gatew_h[i] = __float2half(gw[i]);
}

// ---------------- Kernel 1: tfeat ----------------
__global__ void k_tfeat(const float* __restrict__ tXin,
                        const float* __restrict__ tpw,
                        const float* __restrict__ tpb) {
    __shared__ float s_mean[Dc];
    int b = blockIdx.x;
    int d = threadIdx.x;  // 64 threads
    const float* p = tXin + (size_t)b * Nc * Tc * Dc;  // n = 0 slice
    float s = 0.f;
    #pragma unroll
    for (int t = 0; t < Tc; t++) s += p[t * Dc + d];
    s_mean[d] = s * (1.0f / Tc);
    __syncthreads();
    if (d < Mc) {
        float acc = tpb[d];
        #pragma unroll
        for (int i = 0; i < Dc; i++) acc += s_mean[i] * tpw[i * Mc + d];
        g_tfeat[b * Mc + d] = tanhf(acc);
    }
}

// ---------------- Kernel 2: support GEMM + GCN, tensor cores --------------------
__global__ __launch_bounds__(256) void k_gcn(const float* __restrict__ matrix,
                                             const float* __restrict__ hidden,
                                             const float* __restrict__ gcn_w,
                                             const float* __restrict__ gcn_b) {
    __shared__ __half sA[64][40];
    __shared__ __half sB[32][72];
    __shared__ __half sS[64][72];
    __shared__ __half sW[64][72];
    int tid = threadIdx.x, lane = tid & 31, warp = tid >> 5;
    int nt = blockIdx.x, t = blockIdx.y, b = blockIdx.z;
    int n0 = nt * 64;

    for (int idx = tid; idx < 4096; idx += 256)
        sW[idx >> 6][idx & 63] = __float2half(gcn_w[idx]);

    const float* Mrow = matrix + ((size_t)(b * Tc + t) * Nc) * Nc;

    unsigned sA_b = (unsigned)__cvta_generic_to_shared(&sA[0][0]);
    unsigned sB_b = (unsigned)__cvta_generic_to_shared(&sB[0][0]);
    unsigned sS_b = (unsigned)__cvta_generic_to_shared(&sS[0][0]);
    unsigned sW_b = (unsigned)__cvta_generic_to_shared(&sW[0][0]);

    int r0 = (warp >> 1) * 16;
    int c0 = (warp & 1) * 32;
    int arow = (lane & 7) + (lane & 8);
    int acol8 = (lane & 16) ? 8 : 0;
    int trow = lane >> 2, p2 = lane & 3;

    float acc[4][4] = {};
    for (int kc = 0; kc < 11; kc++) {
        int m0 = kc * 32;
        __syncthreads();
        for (int idx = tid; idx < 2048; idx += 256) {
            int i = idx >> 5, j = idx & 31;
            int n = n0 + i, m = m0 + j;
            float v = (n < Nc && m < Nc) ? Mrow[(size_t)n * Nc + m] : 0.f;
            sA[i][j] = __float2half(v);
        }
        for (int idx = tid; idx < 2048; idx += 256) {
            int j = idx >> 6, d = idx & 63;
            int m = m0 + j;
            float v = (m < Nc) ? hidden[((size_t)(b * Nc + m) * Tc + t) * Dc + d] : 0.f;
            sB[j][d] = __float2half(v);
        }
        __syncthreads();
        #pragma unroll
        for (int ks = 0; ks < 2; ks++) {
            unsigned af[4], bf0[4], bf1[4];
            ldsm_x4(af,    sA_b + ((r0 + arow) * 40 + ks * 16 + acol8) * 2);
            ldsm_x4_t(bf0, sB_b + ((ks * 16 + arow) * 72 + c0 + acol8) * 2);
            ldsm_x4_t(bf1, sB_b + ((ks * 16 + arow) * 72 + c0 + 16 + acol8) * 2);
            mma16816(acc[0], af, bf0[0], bf0[1]);
            mma16816(acc[1], af, bf0[2], bf0[3]);
            mma16816(acc[2], af, bf1[0], bf1[1]);
            mma16816(acc[3], af, bf1[2], bf1[3]);
        }
    }

    #pragma unroll
    for (int ntile = 0; ntile < 4; ntile++) {
        int col = c0 + ntile * 8 + 2 * p2;
        *(__half2*)&sS[r0 + trow][col]     = __floats2half2_rn(acc[ntile][0], acc[ntile][1]);
        *(__half2*)&sS[r0 + trow + 8][col] = __floats2half2_rn(acc[ntile][2], acc[ntile][3]);
    }
    __syncthreads();

    float acc2[4][4] = {};
    #pragma unroll
    for (int ks = 0; ks < 4; ks++) {
        unsigned af[4], bf0[4], bf1[4];
        ldsm_x4(af,    sS_b + ((r0 + arow) * 72 + ks * 16 + acol8) * 2);
        ldsm_x4_t(bf0, sW_b + ((ks * 16 + arow) * 72 + c0 + acol8) * 2);
        ldsm_x4_t(bf1, sW_b + ((ks * 16 + arow) * 72 + c0 + 16 + acol8) * 2);
        mma16816(acc2[0], af, bf0[0], bf0[1]);
        mma16816(acc2[1], af, bf0[2], bf0[3]);
        mma16816(acc2[2], af, bf1[0], bf1[1]);
        mma16816(acc2[3], af, bf1[2], bf1[3]);
    }

    #pragma unroll
    for (int ntile = 0; ntile < 4; ntile++) {
        int col = c0 + ntile * 8 + 2 * p2;
        float bx = gcn_b[col], by = gcn_b[col + 1];
        int n1 = n0 + r0 + trow, n2 = n1 + 8;
        if (n1 < Nc) {
            float2 o = make_float2(fmaxf(acc2[ntile][0] + bx, 0.f),
                                   fmaxf(acc2[ntile][1] + by, 0.f));
            *(float2*)&g_gcn[((size_t)(b * Nc + n1) * Tc + t) * Dc + col] = o;
        }
        if (n2 < Nc) {
            float2 o = make_float2(fmaxf(acc2[ntile][2] + bx, 0.f),
                                   fmaxf(acc2[ntile][3] + by, 0.f));
            *(float2*)&g_gcn[((size_t)(b * Nc + n2) * Tc + t) * Dc + col] = o;
        }
    }
}

// ---------------- Kernel 3: Weff build on tensor cores --------------------------
// Weff[X, bn, :] = emb[bn, :16] @ W[X]  -> (2600x16)@(16x16384) GEMM per X, fp16 out.
// Block: 64 bn rows x 512 cols. Warp: 16-bn tile x 256 cols.
__global__ __launch_bounds__(256) void k_weff(const float* __restrict__ WQ,
                                              const float* __restrict__ WK,
                                              const float* __restrict__ WV,
                                              const float* __restrict__ node_emb) {
    __shared__ __half s_w[16][520];    // 16 k x 512 n (+8 pad), rows 1040B
    __shared__ __half s_emb[64][24];   // 64 bn x 16 m (+8 pad), rows 48B
    int tid = threadIdx.x, lane = tid & 31, warp = tid >> 5;
    int cx = blockIdx.x;   // 32 chunks of 512 cols
    int by = blockIdx.y;   // 41 groups of 64 bn rows
    int X  = blockIdx.z;
    const float* W = (X == 0) ? WQ : (X == 1) ? WK : WV;

    // stage W chunk fp32->fp16: 16 rows x 512 cols = 2048 float4
    for (int i = tid; i < 2048; i += 256) {
        int r = i >> 7, c4 = (i & 127) * 4;
        float4 v = *(const float4*)&W[(size_t)r * 16384 + cx * 512 + c4];
        *(__half2*)&s_w[r][c4]     = __floats2half2_rn(v.x, v.y);
        *(__half2*)&s_w[r][c4 + 2] = __floats2half2_rn(v.z, v.w);
    }
    // stage emb fp16 (zero for bn >= BNc)
    for (int i = tid; i < 1024; i += 256) {
        int row = i >> 4, m = i & 15;
        int bn = by * 64 + row;
        float e = 0.f;
        if (bn < BNc) {
            int b = bn / Nc, n = bn - b * Nc;
            e = node_emb[n * Mc + m] * g_tfeat[b * Mc + m];
        }
        s_emb[row][m] = __float2half(e);
    }
    __syncthreads();

    int tw = warp >> 1, ch = warp & 1;      // 4 bn-tiles x 2 col halves (256)
    int arow = (lane & 7) + (lane & 8);
    int acol = (lane & 16) ? 8 : 0;
    unsigned emb_b = (unsigned)__cvta_generic_to_shared(&s_emb[0][0]);
    unsigned w_b   = (unsigned)__cvta_generic_to_shared(&s_w[0][0]);

    unsigned aF[4];
    ldsm_x4(aF, emb_b + ((tw * 16 + arow) * 24 + acol) * 2);

    int trow = lane >> 2, p2 = lane & 3;
    int bn0 = by * 64 + tw * 16;
    bool ok0 = (bn0 + trow) < BNc;
    bool ok1 = (bn0 + trow + 8) < BNc;
    size_t orow = ((size_t)X * BNc + bn0) * 16384 + cx * 512 + ch * 256;
    __half* o0 = g_weff + orow + (size_t)trow * 16384;
    __half* o1 = g_weff + orow + (size_t)(trow + 8) * 16384;

    #pragma unroll
    for (int it = 0; it < 16; it++) {
        unsigned bF[4];
        ldsm_x4_t(bF, w_b + (arow * 520 + ch * 256 + it * 16 + acol) * 2);
        float c0[4] = {}, c1[4] = {};
        mma16816(c0, aF, bF[0], bF[1]);
        mma16816(c1, aF, bF[2], bF[3]);
        int colo = it * 16 + 2 * p2;
        if (ok0) {
            *(__half2*)&o0[colo]     = __floats2half2_rn(c0[0], c0[1]);
            *(__half2*)&o0[colo + 8] = __floats2half2_rn(c1[0], c1[1]);
        }
        if (ok1) {
            *(__half2*)&o1[colo]     = __floats2half2_rn(c0[2], c0[3]);
            *(__half2*)&o1[colo + 8] = __floats2half2_rn(c1[2], c1[3]);
        }
    }
}

// ---------------- Kernel 4: fused per-(b,n) attention path ----------------------
// smem (float units), total 10752 floats = 43008B (4 CTAs/SM):
//   [0, 2176)      s_act fp16 32x136 (proj)   | s_valh fp16 32x136 overlay (epilogue)
//   [2176, 4224)   proj per-warp weight slabs | s_wb epilogue weight stage 2x1152 halfs
//   [4224, 6400)   s_qh fp16 32x136           | s_gateh fp16 32x136 [gcn|value] overlay
//   [6400, 8576)   s_kh fp16 32x136
//   [8576, 10752)  s_vh fp16 32x136
#define ATTN_SMEM_FLOATS 10752
#define ATTN_SMEM_BYTES  (ATTN_SMEM_FLOATS * 4)

__global__ __launch_bounds__(256, 4) void k_attn(const float* __restrict__ hidden,
                                                 const float* __restrict__ tXin,
                                                 const float* __restrict__ out_b,
                                                 const float* __restrict__ gate_b,
                                                 float* __restrict__ out) {
    extern __shared__ float sm[];
    __half* s_act   = (__half*)sm;              // 32x136 halfs
    __half* s_qh    = (__half*)(sm + 4224);
    __half* s_kh    = (__half*)(sm + 6400);
    __half* s_vh    = (__half*)(sm + 8576);
    __half* s_valh  = s_act;                    // overlay (epilogue)
    __half* s_gateh = s_qh;                     // overlay (epilogue) [gcn | value]

    int tid  = threadIdx.x;
    int lane = tid & 31;
    int warp = tid >> 5;
    int bn   = blockIdx.x;
    size_t base = (size_t)bn * (Tc * Dc);

    // ---- stage activations as fp16 (rows 24-31 zero) ----
    for (int idx = tid; idx < 4096; idx += 256) {
        int t = idx >> 7, i = idx & 127;
        float vv = 0.f;
        if (t < Tc) vv = (i < 64) ? hidden[base + t * 64 + i] : tXin[base + t * 64 + (i - 64)];
        s_act[t * 136 + i] = __float2half(vv);
    }

    const __half* wq = g_weff + (size_t)bn * 16384;
    const __half* wk = g_weff + ((size_t)BNc + bn) * 16384;
    const __half* wv = g_weff + ((size_t)2 * BNc + bn) * 16384;

    unsigned act_base = (unsigned)__cvta_generic_to_shared(s_act);
    unsigned wp_base  = act_base + 2176 * 4 + warp * 1024;  // 2 bufs x 512B per warp
    unsigned swb      = act_base + 2176 * 4;                // epilogue stage base

    int wn = warp * 16;
    int wl_r = lane >> 1, wl_c = lane & 1;
    unsigned wdst_off = wl_r * 32 + wl_c * 16;
    int wsrc_off = wl_r * 128 + wn + wl_c * 8;

    CP_ASYNC16(wp_base + wdst_off, wq + wsrc_off);
    CP_COMMIT();

    int arow = (lane & 7) + (lane & 8);          // 0..15
    int acol = (lane & 16) ? 8 : 0;
    unsigned a_off0 = (arow * 136 + acol) * 2;
    unsigned a_off1 = ((16 + arow) * 136 + acol) * 2;
    unsigned wb_off = arow * 32 + acol * 2;

    int trow = lane >> 2, tcol = (lane & 3) * 2;
    int p2 = lane & 3, ql = lane >> 2;

    __syncthreads();   // s_act visible

    // ---- QKV projection: warp-local double-buffered pipeline ----
    int buf = 0;
    for (int X = 0; X < 3; X++) {
        float acc[2][2][4] = {};
        for (int kk = 0; kk < 8; kk++) {
            int s = X * 8 + kk;
            if (s < 23) {
                int s1 = s + 1;
                int X1 = s1 >> 3, i0 = (s1 & 7) * 16;
                const __half* w = (X1 == 0) ? wq : (X1 == 1) ? wk : wv;
                CP_ASYNC16(wp_base + (buf ^ 1) * 512 + wdst_off, w + i0 * 128 + wsrc_off);
                CP_COMMIT();
                CP_WAIT1();
            } else {
                CP_WAIT0();
            }
            __syncwarp();

            unsigned a0f[4], a1f[4], bf[4];
            ldsm_x4(a0f, act_base + a_off0 + kk * 32);
            ldsm_x4(a1f, act_base + a_off1 + kk * 32);
            ldsm_x4_t(bf, wp_base + buf * 512 + wb_off);
            mma16816(acc[0][0], a0f, bf[0], bf[1]);
            mma16816(acc[0][1], a1f, bf[0], bf[1]);
            mma16816(acc[1][0], a0f, bf[2], bf[3]);
            mma16816(acc[1][1], a1f, bf[2], bf[3]);

            buf ^= 1;
        }
        __half* dst = (X == 0) ? s_qh : (X == 1) ? s_kh : s_vh;
        #pragma unroll
        for (int nt = 0; nt < 2; nt++) {
            int colb = wn + nt * 8 + tcol;
            float* c0p = acc[nt][0];
            *(__half2*)&dst[trow * 136 + colb] = __floats2half2_rn(lrelu(c0p[0]), lrelu(c0p[1]));
            *(__half2*)&dst[(trow + 8) * 136 + colb] = __floats2half2_rn(lrelu(c0p[2]), lrelu(c0p[3]));
            float* c1p = acc[nt][1];
            *(__half2*)&dst[(16 + trow) * 136 + colb] = __floats2half2_rn(lrelu(c1p[0]), lrelu(c1p[1]));
        }
    }

    // all warps done with s_act + proj slabs before overlays are written
    __syncthreads();

    // ================= warp-local attention: head h = warp ======================
    float val[2][2][4] = {};
    {
        int h = warp;
        {
            int r = 24 + (lane >> 2);
            int cu = (lane & 3) * 2;
            unsigned* vz = (unsigned*)s_vh;
            vz[r * 68 + h * 8 + cu]     = 0u;
            vz[r * 68 + h * 8 + cu + 1] = 0u;
        }
        __syncwarp();

        unsigned qh_base = act_base + 4224 * 4;
        unsigned kh_base = act_base + 6400 * 4;
        unsigned vh_base = act_base + 8576 * 4;
        unsigned hcol_off = (arow * 136 + h * 16 + acol) * 2;

        unsigned kq0[4], kq1[4], kb0[4], kb1[4];
        ldsm_x4(kq0, qh_base + hcol_off);
        ldsm_x4(kq1, qh_base + hcol_off + 16 * 272);
        ldsm_x4(kb0, kh_base + hcol_off);
        ldsm_x4(kb1, kh_base + hcol_off + 16 * 272);

        float sc[2][3][4] = {};
        mma16816(sc[0][0], kq0, kb0[0], kb0[2]);
        mma16816(sc[0][1], kq0, kb0[1], kb0[3]);
        mma16816(sc[0][2], kq0, kb1[0], kb1[2]);
        mma16816(sc[1][0], kq1, kb0[0], kb0[2]);
        mma16816(sc[1][1], kq1, kb0[1], kb0[3]);
        mma16816(sc[1][2], kq1, kb1[0], kb1[2]);

        unsigned ah[3][3];
        #pragma unroll
        for (int g = 0; g < 3; g++) {
            int t = ql + 8 * g;
            float x[6];
            #pragma unroll
            for (int nt = 0; nt < 3; nt++) {
                #pragma unroll
                for (int p = 0; p < 2; p++) {
                    float raw = (g == 0) ? sc[0][nt][p]
                              : (g == 1) ? sc[0][nt][2 + p]
                                         : sc[1][nt][p];
                    int scol = nt * 8 + 2 * p2 + p;
                    x[nt * 2 + p] = (scol <= t) ? 0.25f * raw : -1e30f;
                }
            }
            float mx = x[0];
            #pragma unroll
            for (int j = 1; j < 6; j++) mx = fmaxf(mx, x[j]);
            mx = fmaxf(mx, __shfl_xor_sync(0xFFFFFFFF, mx, 1));
            mx = fmaxf(mx, __shfl_xor_sync(0xFFFFFFFF, mx, 2));
            float e[6], sum = 0.f;
            #pragma unroll
            for (int j = 0; j < 6; j++) { e[j] = __expf(x[j] - mx); sum += e[j]; }
            sum += __shfl_xor_sync(0xFFFFFFFF, sum, 1);
            sum += __shfl_xor_sync(0xFFFFFFFF, sum, 2);
            float inv = 1.f / sum;
            #pragma unroll
            for (int nt = 0; nt < 3; nt++)
                ah[g][nt] = packh2(e[nt * 2] * inv, e[nt * 2 + 1] * inv);
        }

        unsigned vb0[4], vb1[4];
        ldsm_x4_t(vb0, vh_base + hcol_off);
        ldsm_x4_t(vb1, vh_base + hcol_off + 16 * 272);

        unsigned A00[4] = { ah[0][0], ah[1][0], ah[0][1], ah[1][1] };
        unsigned A01[4] = { ah[2][0], 0u,       ah[2][1], 0u       };
        unsigned A10[4] = { ah[0][2], ah[1][2], 0u,       0u       };
        unsigned A11[4] = { ah[2][2], 0u,       0u,       0u       };

        #pragma unroll
        for (int ne = 0; ne < 2; ne++) {
            mma16816(val[0][ne], A00, vb0[2 * ne], vb0[2 * ne + 1]);
            mma16816(val[0][ne], A10, vb1[2 * ne], vb1[2 * ne + 1]);
            mma16816(val[1][ne], A01, vb0[2 * ne], vb0[2 * ne + 1]);
            mma16816(val[1][ne], A11, vb1[2 * ne], vb1[2 * ne + 1]);
        }

        // store val as fp16 into s_valh (own 16 cols); zero pad rows 24-31
        {
            int zr = 24 + (lane >> 2);         // rows 24..31
            int zc = (lane & 3) * 4;           // 4 halfs
            *(float2*)&s_valh[zr * 136 + h * 16 + zc] = make_float2(0.f, 0.f);
        }
        #pragma unroll
        for (int ne = 0; ne < 2; ne++) {
            int colf = h * 16 + ne * 8 + 2 * p2;
            *(__half2*)&s_valh[ql * 136 + colf]        = __floats2half2_rn(val[0][ne][0], val[0][ne][1]);
            *(__half2*)&s_valh[(ql + 8) * 136 + colf]  = __floats2half2_rn(val[0][ne][2], val[0][ne][3]);
            *(__half2*)&s_valh[(16 + ql) * 136 + colf] = __floats2half2_rn(val[1][ne][0], val[1][ne][1]);
        }
    }

    // ---- stage gcn fp16 into s_gateh cols 0-63; zero rows 24-31 (all 128 cols) ----
    __syncthreads();

    for (int idx = tid; idx < 1536; idx += 256) {
        int t = idx >> 6, d = idx & 63;
        s_gateh[t * 136 + d] = __float2half(g_gcn[base + idx]);
    }
    for (int idx = tid; idx < 1024; idx += 256) {
        int r = 24 + (idx >> 7), c = idx & 127;
        s_gateh[r * 136 + c] = __float2half(0.f);
    }

    // ================= epilogue on tensor cores =================================
    int mg = warp >> 2, ng = warp & 3;     // 2 m-tiles x 4 n-tiles (16 cols each)
    unsigned aV_off = ((mg * 16 + arow) * 136 + acol) * 2;
    unsigned bW_off = (arow * 72 + ng * 16 + acol) * 2;
    int st_r = tid >> 3, st_s = tid & 7;   // staging: threads<128: 16 rows x 8 segs
    unsigned st_dst = st_r * 144 + st_s * 16;
    int st_src = st_r * 64 + st_s * 8;

    // prefetch out_w chunk 0
    if (tid < 128) CP_ASYNC16(swb + st_dst, g_outw_h + st_src);
    CP_COMMIT();

    float vacc[2][4] = {};
    int ebuf = 0;
    for (int kk = 0; kk < 8; kk++) {
        if (kk < 7) {
            if (tid < 128) CP_ASYNC16(swb + (ebuf ^ 1) * 2304 + st_dst,
                                      g_outw_h + (kk + 1) * 1024 + st_src);
            CP_COMMIT();
            CP_WAIT1();
        } else {
            CP_WAIT0();
        }
        __syncthreads();
        unsigned aF[4], bF[4];
        ldsm_x4(aF, act_base + aV_off + kk * 32);
        ldsm_x4_t(bF, swb + ebuf * 2304 + bW_off);
        mma16816(vacc[0], aF, bF[0], bF[1]);
        mma16816(vacc[1], aF, bF[2], bF[3]);
        __syncthreads();
        ebuf ^= 1;
    }

    // value = lrelu(vacc + out_b); keep in regs; store fp16 into s_gateh cols 64+
    float vv_[2][4];
    #pragma unroll
    for (int nt = 0; nt < 2; nt++) {
        int col = ng * 16 + nt * 8 + 2 * p2;
        float bx = out_b[col], by = out_b[col + 1];
        vv_[nt][0] = lrelu(vacc[nt][0] + bx);
        vv_[nt][1] = lrelu(vacc[nt][1] + by);
        vv_[nt][2] = lrelu(vacc[nt][2] + bx);
        vv_[nt][3] = lrelu(vacc[nt][3] + by);
        int r0a = mg * 16 + trow;            // always < 24
        int r1a = r0a + 8;                   // valid only for mg==0
        *(__half2*)&s_gateh[r0a * 136 + 64 + col] = __floats2half2_rn(vv_[nt][0], vv_[nt][1]);
        if (mg == 0)
            *(__half2*)&s_gateh[r1a * 136 + 64 + col] = __floats2half2_rn(vv_[nt][2], vv_[nt][3]);
    }
    __syncthreads();

    // prefetch gate_w chunk 0
    if (tid < 128) CP_ASYNC16(swb + st_dst, g_gatew_h + st_src);
    CP_COMMIT();

    float gacc[2][4] = {};
    ebuf = 0;
    for (int kk = 0; kk < 8; kk++) {
        if (kk < 7) {
            if (tid < 128) CP_ASYNC16(swb + (ebuf ^ 1) * 2304 + st_dst,
                                      g_gatew_h + (kk + 1) * 1024 + st_src);
            CP_COMMIT();
            CP_WAIT1();
        } else {
            CP_WAIT0();
        }
        __syncthreads();
        unsigned aF[4], bF[4];
        ldsm_x4(aF, act_base + 4224 * 4 + aV_off + kk * 32);   // s_gateh
        ldsm_x4_t(bF, swb + ebuf * 2304 + bW_off);
        mma16816(gacc[0], aF, bF[0], bF[1]);
        mma16816(gacc[1], aF, bF[2], bF[3]);
        __syncthreads();
        ebuf ^= 1;
    }

    // ---- blend + residual, straight from fragments ----
    #pragma unroll
    for (int nt = 0; nt < 2; nt++) {
        int col = ng * 16 + nt * 8 + 2 * p2;
        float bgx = gate_b[col], bgy = gate_b[col + 1];
        int r0a = mg * 16 + trow;
        {
            float zx = 1.f / (1.f + __expf(-(gacc[nt][0] + bgx)));
            float zy = 1.f / (1.f + __expf(-(gacc[nt][1] + bgy)));
            float2 gc = __half22float2(*(__half2*)&s_gateh[r0a * 136 + col]);
            float2 hd = *(const float2*)&hidden[base + r0a * 64 + col];
            float2 o;
            o.x = zx * gc.x + (1.f - zx) * vv_[nt][0] + hd.x;
            o.y = zy * gc.y + (1.f - zy) * vv_[nt][1] + hd.y;
            *(float2*)&out[base + r0a * 64 + col] = o;
        }
        if (mg == 0) {
            int r1a = r0a + 8;
            float zx = 1.f / (1.f + __expf(-(gacc[nt][2] + bgx)));
            float zy = 1.f / (1.f + __expf(-(gacc[nt][3] + bgy)));
            float2 gc = __half22float2(*(__half2*)&s_gateh[r1a * 136 + col]);
            float2 hd = *(const float2*)&hidden[base + r1a * 64 + col];
            float2 o;
            o.x = zx * gc.x + (1.f - zx) * vv_[nt][2] + hd.x;
            o.y = zy * gc.y + (1.f - zy) * vv_[nt][3] + hd.y;
            *(float2*)&out[base + r1a * 64 + col] = o;
        }
    }
}

// ---------------- launch ----------------
extern "C" void kernel_launch(void* const* d_in, const int* in_sizes, int n_in,
                              void* d_out, int out_size) {
    const float* hidden   = (const float*)d_in[0];
    const float* tXin     = (const float*)d_in[1];
    const float* matrix   = (const float*)d_in[2];
    const float* gcn_w    = (const float*)d_in[3];
    const float* gcn_b    = (const float*)d_in[4];
    const float* node_emb = (const float*)d_in[5];
    const float* tproj_w  = (const float*)d_in[6];
    const float* tproj_b  = (const float*)d_in[7];
    const float* WK       = (const float*)d_in[8];
    const float* WQ       = (const float*)d_in[9];
    const float* WV       = (const float*)d_in[10];
    const float* out_w    = (const float*)d_in[11];
    const float* out_b    = (const float*)d_in[12];
    const float* gate_w   = (const float*)d_in[13];
    const float* gate_b   = (const float*)d_in[14];
    float* out = (float*)d_out;

    cudaFuncSetAttribute(k_attn, cudaFuncAttributeMaxDynamicSharedMemorySize, ATTN_SMEM_BYTES);

    k_tfeat<<<Bc, 64>>>(tXin, tproj_w, tproj_b);
    k_prep<<<32, 256>>>(out_w, gate_w);
    k_gcn<<<dim3(6, Tc, Bc), 256>>>(matrix, hidden, gcn_w, gcn_b);
    k_weff<<<dim3(32, 41, 3), 256>>>(WQ, WK, WV, node_emb);
    k_attn<<<BNc, 256, ATTN_SMEM_BYTES>>>(hidden, tXin, out_b, gate_b, out);
}